// round 13
// baseline (speedup 1.0000x reference)
#include <cuda_runtime.h>

// ---------------------------------------------------------------------------
// GATv2 (H=2, EMB=64) + fused final linear, collapsed to scalar-per-edge form.
// R13: warp-autonomous k_nodes_out — per-lane S in registers, shfl broadcast,
//      no inter-phase block barrier (R12 showed barrier-coupled latency, not
//      bandwidth, bound the 16us). Edges = R12-exact (FFMA2-pipe floor).
//
// Per-edge:  logit_h = 0.6*L_h + 0.4*sum_c att_hc*|z_hc|   (LeakyReLU split)
//            z_hc = s*Wl + t*Wr + a*We + b,  L_h = s*P_h + t*Q_h + a*R_h + B_h
// Per-node:  S_ih = sum_e alpha_eh * x[src_e]   (softmax without max-shift)
// Output:    out[i,:] = S_i0*A0 + S_i1*A1 + (CB + T0*D0 + T1*D1)
// ---------------------------------------------------------------------------

#define NODE_CAP 131072
#define EPT 4

typedef unsigned long long u64;

__device__ float4 g_accum[NODE_CAP];    // {den0, num0, den1, num1}
__device__ float2 g_degattr[NODE_CAP];  // {deg, attr_sum}

// --- edge weights, head-packed f32x2 (lo=head0, hi=head1), natural order
__device__ ulonglong2 g_eA[64];   // {wl2, wr2}
__device__ ulonglong2 g_eB[64];   // {we2, b2}
__device__ u64 g_em[64];          // per-half sign masks of att
__device__ u64 g_lin[4];          // P, Q, R, B head-packed

// --- node (self-loop) weights, head-packed, natural order
__device__ ulonglong2 g_nA[64];   // {wlr2, we2}
__device__ ulonglong2 g_nB[64];   // {b2, m2}
__device__ u64 g_nlpq, g_nlr, g_nlb;

// --- final linear vectors
__device__ __align__(16) float g_A0[128];
__device__ __align__(16) float g_A1[128];
__device__ __align__(16) float g_CB[128];
__device__ __align__(16) float g_D0[128];
__device__ __align__(16) float g_D1[128];
__device__ __align__(16) float g_Cv[128];   // CB + T0*D0 + T1*D1 (k_tgt)
__device__ int g_idx64;

// ---- f32x2 helpers ----
__device__ __forceinline__ u64 pack2(float lo, float hi) {
    u64 r;
    asm("mov.b64 %0, {%1, %2};" : "=l"(r) : "r"(__float_as_uint(lo)), "r"(__float_as_uint(hi)));
    return r;
}
__device__ __forceinline__ void unpack2(u64 v, float& lo, float& hi) {
    unsigned a, b;
    asm("mov.b64 {%0, %1}, %2;" : "=r"(a), "=r"(b) : "l"(v));
    lo = __uint_as_float(a); hi = __uint_as_float(b);
}
__device__ __forceinline__ u64 fma2(u64 a, u64 b, u64 c) {
    u64 d;
    asm("fma.rn.f32x2 %0, %1, %2, %3;" : "=l"(d) : "l"(a), "l"(b), "l"(c));
    return d;
}
__device__ __forceinline__ u64 add2(u64 a, u64 b) {
    u64 d;
    asm("add.rn.f32x2 %0, %1, %2;" : "=l"(d) : "l"(a), "l"(b));
    return d;
}
// per 32-bit half: (z & 0x7fffffff) | mask   (LOP3, immLut 0xEA)
__device__ __forceinline__ u64 abso2(u64 z, unsigned mlo, unsigned mhi) {
    unsigned lo, hi, rlo, rhi;
    asm("mov.b64 {%0, %1}, %2;" : "=r"(lo), "=r"(hi) : "l"(z));
    asm("lop3.b32 %0, %1, 0x7fffffff, %2, 0xEA;" : "=r"(rlo) : "r"(lo), "r"(mlo));
    asm("lop3.b32 %0, %1, 0x7fffffff, %2, 0xEA;" : "=r"(rhi) : "r"(hi), "r"(mhi));
    u64 r;
    asm("mov.b64 %0, {%1, %2};" : "=l"(r) : "r"(rlo), "r"(rhi));
    return r;
}
__device__ __forceinline__ float ex2f(float x) {
    float r;
    asm("ex2.approx.f32 %0, %1;" : "=f"(r) : "f"(x));
    return r;
}

// ---------------------------------------------------------------------------
// launch 0: merged setup.
//   block 0:        weight prep (edge arrays, node arrays, lin, dtype detect)
//   blocks 1..16:   final-linear vectors (warp per output row)
//   blocks 17+:     zero node accumulators
__global__ void __launch_bounds__(256) k_setup(
    const void* __restrict__ eidx, int n,
    const float* __restrict__ Wl, const float* __restrict__ bl,
    const float* __restrict__ Wr, const float* __restrict__ br,
    const float* __restrict__ We, const float* __restrict__ att,
    const float* __restrict__ bout, const float* __restrict__ Wfc,
    const float* __restrict__ bfc)
{
    const float LOG2E = 1.4426950408889634f;
    const float kap = 0.4f * LOG2E;
    const float lam = 0.6f * LOG2E;
    int bid = blockIdx.x;
    int tid = threadIdx.x;

    if (bid >= 17) {                 // zeroing
        int i = (bid - 17) * 256 + tid;
        if (i < n) {
            g_accum[i] = make_float4(0.f, 0.f, 0.f, 0.f);
            g_degattr[i] = make_float2(0.f, 0.f);
        }
        return;
    }
    if (bid >= 1) {                  // vecA: warp per output row j
        int lane = tid & 31;
        int j = (bid - 1) * 8 + (tid >> 5);
        const float* wrow = Wfc + j * 256;
        float a0 = 0.f, a1 = 0.f, cb = 0.f, d0 = 0.f, d1 = 0.f;
#pragma unroll
        for (int u = 0; u < 8; u++) {
            int idx = u * 32 + lane;
            float w = wrow[idx];
            if (u < 2) {
                a0 += Wl[idx] * w;
                cb += (bl[idx] + bout[idx]) * w;
            } else if (u < 4) {
                a1 += Wl[idx] * w;
                cb += (bl[idx] + bout[idx]) * w;
            } else if (u < 6) {
                int kk = idx - 128;
                cb += (bl[kk] + bout[kk]) * w;
                d0 += Wl[kk] * w;
            } else {
                int kk = idx - 128;
                cb += (bl[kk] + bout[kk]) * w;
                d1 += Wl[kk] * w;
            }
        }
#pragma unroll
        for (int off = 16; off > 0; off >>= 1) {
            a0 += __shfl_xor_sync(0xffffffffu, a0, off);
            a1 += __shfl_xor_sync(0xffffffffu, a1, off);
            cb += __shfl_xor_sync(0xffffffffu, cb, off);
            d0 += __shfl_xor_sync(0xffffffffu, d0, off);
            d1 += __shfl_xor_sync(0xffffffffu, d1, off);
        }
        if (lane == 0) {
            g_A0[j] = a0; g_A1[j] = a1; g_CB[j] = cb + bfc[j];
            g_D0[j] = d0; g_D1[j] = d1;
        }
        return;
    }

    // block 0: weight prep
    if (tid < 64) {
        int c = tid;
        float a0 = att[c], a1 = att[64 + c];
        float k0 = kap * a0, k1 = kap * a1;
        float wl0 = k0 * Wl[c], wl1 = k1 * Wl[64 + c];
        float wr0 = k0 * Wr[c], wr1 = k1 * Wr[64 + c];
        float we0 = k0 * We[c], we1 = k1 * We[64 + c];
        float b0 = k0 * (bl[c] + br[c]), b1 = k1 * (bl[64 + c] + br[64 + c]);
        unsigned m0 = __float_as_uint(a0) & 0x80000000u;
        unsigned m1 = __float_as_uint(a1) & 0x80000000u;
        u64 m2 = ((u64)m1 << 32) | (u64)m0;
        ulonglong2 eA; eA.x = pack2(wl0, wl1); eA.y = pack2(wr0, wr1);
        ulonglong2 eB; eB.x = pack2(we0, we1); eB.y = pack2(b0, b1);
        g_eA[c] = eA; g_eB[c] = eB; g_em[c] = m2;
        ulonglong2 nA; nA.x = pack2(wl0 + wr0, wl1 + wr1); nA.y = eB.x;
        ulonglong2 nB; nB.x = eB.y; nB.y = m2;
        g_nA[c] = nA; g_nB[c] = nB;
    }
    if (tid == 0) {
        float Ph[2], Qh[2], Rh[2], Bh[2];
        for (int h = 0; h < 2; h++) {
            float P = 0, Q = 0, R = 0, B = 0;
            for (int c = 0; c < 64; c++) {
                int j = h * 64 + c;
                float aA = att[j];
                P += aA * Wl[j]; Q += aA * Wr[j]; R += aA * We[j];
                B += aA * (bl[j] + br[j]);
            }
            Ph[h] = lam * P; Qh[h] = lam * Q; Rh[h] = lam * R; Bh[h] = lam * B;
        }
        g_lin[0] = pack2(Ph[0], Ph[1]);
        g_lin[1] = pack2(Qh[0], Qh[1]);
        g_lin[2] = pack2(Rh[0], Rh[1]);
        g_lin[3] = pack2(Bh[0], Bh[1]);
        g_nlpq = pack2(Ph[0] + Qh[0], Ph[1] + Qh[1]);
        g_nlr  = g_lin[2];
        g_nlb  = g_lin[3];
        // edge_index dtype detection (int64 values all < n)
        const u64* p = (const u64*)eidx;
        int is64 = 1;
        for (int k = 0; k < 16; k++)
            if (p[k] >= (u64)n) is64 = 0;
        g_idx64 = is64;
    }
}

// ---------------------------------------------------------------------------
// launch 1: edge pass (R7/R12-exact: EPT=4, at the FFMA2-pipe floor)
__global__ void __launch_bounds__(256, 2) k_edges(
    const float* __restrict__ x, const void* __restrict__ eidx,
    const float* __restrict__ eattr, int E)
{
    __shared__ ulonglong2 s_eA[64], s_eB[64];
    __shared__ u64 s_m[64];
    int tid = threadIdx.x;
    if (tid < 64) { s_eA[tid] = g_eA[tid]; s_eB[tid] = g_eB[tid]; s_m[tid] = g_em[tid]; }
    __syncthreads();

    int base = (blockIdx.x * blockDim.x + tid) * EPT;
    if (base >= E) return;
    int idx64 = g_idx64;
    const long long* p64 = (const long long*)eidx;
    const int* p32 = (const int*)eidx;

    u64 s2[EPT], t2[EPT], a2[EPT], acc[EPT];
    int dsti[EPT];

#pragma unroll
    for (int k = 0; k < EPT; k++) {
        int e = base + k; if (e > E - 1) e = E - 1;
        int si, di;
        if (idx64) { si = (int)p64[e]; di = (int)p64[E + e]; }
        else       { si = p32[e];      di = p32[E + e]; }
        dsti[k] = di;
        float aa = eattr[e];
        float s = x[si], t = x[di];
        s2[k] = pack2(s, s); t2[k] = pack2(t, t); a2[k] = pack2(aa, aa);
        acc[k] = 0ull;
    }

#pragma unroll 8
    for (int c = 0; c < 64; c++) {
        ulonglong2 wA = s_eA[c];   // {wl, wr}
        ulonglong2 wB = s_eB[c];   // {we, b}
        u64 mm = s_m[c];
        unsigned mlo = (unsigned)mm, mhi = (unsigned)(mm >> 32);
#pragma unroll
        for (int k = 0; k < EPT; k++) {
            u64 z = fma2(a2[k], wB.x, wB.y);
            z = fma2(t2[k], wA.y, z);
            z = fma2(s2[k], wA.x, z);
            acc[k] = add2(acc[k], abso2(z, mlo, mhi));
        }
    }

    u64 P = g_lin[0], Q = g_lin[1], R = g_lin[2], B = g_lin[3];
#pragma unroll
    for (int k = 0; k < EPT; k++) {
        if (base + k >= E) continue;
        u64 f2 = add2(acc[k], B);
        f2 = fma2(a2[k], R, f2);
        f2 = fma2(t2[k], Q, f2);
        f2 = fma2(s2[k], P, f2);
        float f0, f1; unpack2(f2, f0, f1);
        float e0 = ex2f(f0), e1 = ex2f(f1);
        float sv, av, dum;
        unpack2(s2[k], sv, dum);
        unpack2(a2[k], av, dum);
        atomicAdd(&g_degattr[dsti[k]], make_float2(1.0f, av));
        atomicAdd(&g_accum[dsti[k]], make_float4(e0, e0 * sv, e1, e1 * sv));
    }
}

// ---------------------------------------------------------------------------
// launch 2: S[target] + folded constant vector Cv (1 block, 128 threads)
__global__ void k_tgt(const float* __restrict__ x, const int* __restrict__ tgtp)
{
    __shared__ float2 sh_S;
    int tid = threadIdx.x;
    int tgt = tgtp[0];   // low 32 bits valid for int32/int64 (LE)
    if (tid < 32) {
        float s = x[tgt];
        float2 da = g_degattr[tgt];
        float am = da.y / fmaxf(da.x, 1.0f);
        u64 s2 = pack2(s, s), a2 = pack2(am, am);
        u64 acc = 0ull;
        for (int c = tid; c < 64; c += 32) {
            ulonglong2 A = g_nA[c], Bv = g_nB[c];
            u64 z = fma2(a2, A.y, Bv.x);
            z = fma2(s2, A.x, z);
            acc = add2(acc, abso2(z, (unsigned)Bv.y, (unsigned)(Bv.y >> 32)));
        }
        float h0, h1; unpack2(acc, h0, h1);
#pragma unroll
        for (int off = 16; off > 0; off >>= 1) {
            h0 += __shfl_xor_sync(0xffffffffu, h0, off);
            h1 += __shfl_xor_sync(0xffffffffu, h1, off);
        }
        u64 f = add2(pack2(h0, h1), fma2(s2, g_nlpq, fma2(a2, g_nlr, g_nlb)));
        float f0, f1; unpack2(f, f0, f1);
        float e0 = ex2f(f0), e1 = ex2f(f1);
        float4 ac = g_accum[tgt];
        if (tid == 0)
            sh_S = make_float2((ac.y + e0 * s) / (ac.x + e0),
                               (ac.w + e1 * s) / (ac.z + e1));
    }
    __syncthreads();
    float2 st = sh_S;
    if (tid < 128)
        g_Cv[tid] = fmaf(st.x, g_D0[tid], fmaf(st.y, g_D1[tid], g_CB[tid]));
}

// ---------------------------------------------------------------------------
// launch 3 (PROFILED): warp-autonomous self-loop/softmax finalize + output.
// Each warp owns 32 nodes. Lane j computes S for node base+j (registers only),
// then 32 shfl-broadcast iterations write the 512B rows. No block barrier
// between phases -> phase-2 stores of one warp overlap phase-1 of others.
__global__ void __launch_bounds__(256) k_nodes_out(
    const float* __restrict__ x, int n, float* __restrict__ out)
{
    __shared__ ulonglong2 s_A[64], s_B[64];
    int tid = threadIdx.x;
    if (tid < 64) { s_A[tid] = g_nA[tid]; s_B[tid] = g_nB[tid]; }
    __syncthreads();   // weight staging only; phases below are warp-local

    int lane = tid & 31;
    int warp = (blockIdx.x * 256 + tid) >> 5;
    int base = warp * 32;
    if (base >= n) return;

    // ---- phase 1: per-lane S for node base+lane ----
    float2 sS;
    {
        int i = base + lane;
        int ii = (i < n) ? i : (n - 1);
        float s = x[ii];
        float2 da = g_degattr[ii];
        float4 ac = g_accum[ii];

        float am = da.y / fmaxf(da.x, 1.0f);
        u64 s2 = pack2(s, s), a2 = pack2(am, am);
        u64 acc0 = 0ull, acc1 = 0ull, acc2 = 0ull, acc3 = 0ull;
#pragma unroll 2
        for (int c = 0; c < 64; c += 4) {
            ulonglong2 A0 = s_A[c],     B0 = s_B[c];
            ulonglong2 A1 = s_A[c + 1], B1 = s_B[c + 1];
            ulonglong2 A2 = s_A[c + 2], B2 = s_B[c + 2];
            ulonglong2 A3 = s_A[c + 3], B3 = s_B[c + 3];
            u64 z0 = fma2(s2, A0.x, fma2(a2, A0.y, B0.x));
            u64 z1 = fma2(s2, A1.x, fma2(a2, A1.y, B1.x));
            u64 z2 = fma2(s2, A2.x, fma2(a2, A2.y, B2.x));
            u64 z3 = fma2(s2, A3.x, fma2(a2, A3.y, B3.x));
            acc0 = add2(acc0, abso2(z0, (unsigned)B0.y, (unsigned)(B0.y >> 32)));
            acc1 = add2(acc1, abso2(z1, (unsigned)B1.y, (unsigned)(B1.y >> 32)));
            acc2 = add2(acc2, abso2(z2, (unsigned)B2.y, (unsigned)(B2.y >> 32)));
            acc3 = add2(acc3, abso2(z3, (unsigned)B3.y, (unsigned)(B3.y >> 32)));
        }
        u64 f = add2(add2(acc0, acc1), add2(acc2, acc3));
        f = add2(f, fma2(s2, g_nlpq, fma2(a2, g_nlr, g_nlb)));
        float f0, f1; unpack2(f, f0, f1);
        float e0 = ex2f(f0), e1 = ex2f(f1);
        sS = make_float2((ac.y + e0 * s) / (ac.x + e0),
                         (ac.w + e1 * s) / (ac.z + e1));
    }

    // ---- phase 2: shfl-broadcast, 512B row per iteration ----
    ulonglong2 A0v = ((const ulonglong2*)g_A0)[lane];
    ulonglong2 A1v = ((const ulonglong2*)g_A1)[lane];
    ulonglong2 Cv  = ((const ulonglong2*)g_Cv)[lane];
    ulonglong2* o2p = (ulonglong2*)out;
    if (base + 32 <= n) {
#pragma unroll 8
        for (int j = 0; j < 32; j++) {
            float sx = __shfl_sync(0xffffffffu, sS.x, j);
            float sy = __shfl_sync(0xffffffffu, sS.y, j);
            u64 sx2 = pack2(sx, sx), sy2 = pack2(sy, sy);
            ulonglong2 o;
            o.x = fma2(sx2, A0v.x, fma2(sy2, A1v.x, Cv.x));
            o.y = fma2(sx2, A0v.y, fma2(sy2, A1v.y, Cv.y));
            o2p[(long long)(base + j) * 32 + lane] = o;
        }
    } else {
        for (int j = 0; j < 32; j++) {
            int node = base + j;
            if (node >= n) break;
            float sx = __shfl_sync(0xffffffffu, sS.x, j);
            float sy = __shfl_sync(0xffffffffu, sS.y, j);
            u64 sx2 = pack2(sx, sx), sy2 = pack2(sy, sy);
            ulonglong2 o;
            o.x = fma2(sx2, A0v.x, fma2(sy2, A1v.x, Cv.x));
            o.y = fma2(sx2, A0v.y, fma2(sy2, A1v.y, Cv.y));
            o2p[(long long)node * 32 + lane] = o;
        }
    }
}

// ---------------------------------------------------------------------------
extern "C" void kernel_launch(void* const* d_in, const int* in_sizes, int n_in,
                              void* d_out, int out_size)
{
    const float* x     = (const float*)d_in[0];
    const void*  eidx  = d_in[1];
    const float* eattr = (const float*)d_in[2];
    const int*   tgtp  = (const int*)d_in[3];
    const float* Wl    = (const float*)d_in[4];
    const float* bl    = (const float*)d_in[5];
    const float* Wr    = (const float*)d_in[6];
    const float* br    = (const float*)d_in[7];
    const float* We    = (const float*)d_in[8];
    const float* att   = (const float*)d_in[9];
    const float* bout  = (const float*)d_in[10];
    const float* Wfc   = (const float*)d_in[11];
    const float* bfc   = (const float*)d_in[12];

    int n = in_sizes[0];   // N nodes (x is [N,1])
    int E = in_sizes[2];   // edges (edge_attr is [E,1])
    float* out = (float*)d_out;

    int nblk = (n + 255) / 256;
    k_setup<<<nblk + 17, 256>>>(eidx, n, Wl, bl, Wr, br, We, att,
                                bout, Wfc, bfc);                 // idx 0
    int ethreads = (E + EPT - 1) / EPT;
    k_edges<<<(ethreads + 255) / 256, 256>>>(x, eidx, eattr, E); // idx 1
    k_tgt<<<1, 128>>>(x, tgtp);                                  // idx 2
    k_nodes_out<<<nblk, 256>>>(x, n, out);                       // idx 3 (profiled)
}

// round 14
// speedup vs baseline: 1.3088x; 1.3088x over previous
#include <cuda_runtime.h>
#include <cuda_fp16.h>

// ---------------------------------------------------------------------------
// GATv2 (H=2, EMB=64) + fused final linear, collapsed to scalar-per-edge form.
// R14: fp16 edge channel-loop. HFMA2 rt=2 with 2 halves/instr = 2x the fp32
//      FMA rate (R11 established rt(FFMA2)=4 => f32 path is pipe-floor-bound
//      at ~48us). Heads packed in half2; 4 fp16 accumulators/edge bound the
//      accumulation error; linear part / exp / atomics / softmax stay fp32.
//      nodes_out = R13 warp-autonomous version (best isolated measurement).
//
// Per-edge:  logit_h = 0.6*L_h + 0.4*sum_c att_hc*|z_hc|   (LeakyReLU split)
//            z_hc = s*Wl + t*Wr + a*We + b,  L_h = s*P_h + t*Q_h + a*R_h + B_h
// Per-node:  S_ih = sum_e alpha_eh * x[src_e]   (softmax without max-shift)
// Output:    out[i,:] = S_i0*A0 + S_i1*A1 + (CB + T0*D0 + T1*D1)
// ---------------------------------------------------------------------------

#define NODE_CAP 131072
#define EPT 4

typedef unsigned long long u64;

__device__ float4 g_accum[NODE_CAP];    // {den0, num0, den1, den1? no: den1, num1}
__device__ float2 g_degattr[NODE_CAP];  // {deg, attr_sum}

// --- edge weights, fp16 head-packed (lo=head0, hi=head1), natural order
__device__ uint4    g_eW[64];     // {wl_h2, wr_h2, we_h2, b_h2}
__device__ unsigned g_eM[64];     // sign-or mask (bit15 head0, bit31 head1)
__device__ float    g_linS[8];    // P0,Q0,R0,B0, P1,Q1,R1,B1 (f32)

// --- node (self-loop) weights, f32 head-packed, natural order
__device__ ulonglong2 g_nA[64];   // {wlr2, we2}
__device__ ulonglong2 g_nB[64];   // {b2, m2}
__device__ u64 g_nlpq, g_nlr, g_nlb;

// --- final linear vectors
__device__ __align__(16) float g_A0[128];
__device__ __align__(16) float g_A1[128];
__device__ __align__(16) float g_CB[128];
__device__ __align__(16) float g_D0[128];
__device__ __align__(16) float g_D1[128];
__device__ __align__(16) float g_Cv[128];   // CB + T0*D0 + T1*D1 (k_tgt)
__device__ int g_idx64;

// ---- f32x2 helpers (node path) ----
__device__ __forceinline__ u64 pack2(float lo, float hi) {
    u64 r;
    asm("mov.b64 %0, {%1, %2};" : "=l"(r) : "r"(__float_as_uint(lo)), "r"(__float_as_uint(hi)));
    return r;
}
__device__ __forceinline__ void unpack2(u64 v, float& lo, float& hi) {
    unsigned a, b;
    asm("mov.b64 {%0, %1}, %2;" : "=r"(a), "=r"(b) : "l"(v));
    lo = __uint_as_float(a); hi = __uint_as_float(b);
}
__device__ __forceinline__ u64 fma2(u64 a, u64 b, u64 c) {
    u64 d;
    asm("fma.rn.f32x2 %0, %1, %2, %3;" : "=l"(d) : "l"(a), "l"(b), "l"(c));
    return d;
}
__device__ __forceinline__ u64 add2(u64 a, u64 b) {
    u64 d;
    asm("add.rn.f32x2 %0, %1, %2;" : "=l"(d) : "l"(a), "l"(b));
    return d;
}
__device__ __forceinline__ u64 abso2(u64 z, unsigned mlo, unsigned mhi) {
    unsigned lo, hi, rlo, rhi;
    asm("mov.b64 {%0, %1}, %2;" : "=r"(lo), "=r"(hi) : "l"(z));
    asm("lop3.b32 %0, %1, 0x7fffffff, %2, 0xEA;" : "=r"(rlo) : "r"(lo), "r"(mlo));
    asm("lop3.b32 %0, %1, 0x7fffffff, %2, 0xEA;" : "=r"(rhi) : "r"(hi), "r"(mhi));
    u64 r;
    asm("mov.b64 %0, {%1, %2};" : "=l"(r) : "r"(rlo), "r"(rhi));
    return r;
}
__device__ __forceinline__ float ex2f(float x) {
    float r;
    asm("ex2.approx.f32 %0, %1;" : "=f"(r) : "f"(x));
    return r;
}

// ---- fp16x2 helpers (edge path) ----
__device__ __forceinline__ unsigned hfma2u(unsigned a, unsigned b, unsigned c) {
    unsigned d;
    asm("fma.rn.f16x2 %0, %1, %2, %3;" : "=r"(d) : "r"(a), "r"(b), "r"(c));
    return d;
}
__device__ __forceinline__ unsigned hadd2u(unsigned a, unsigned b) {
    unsigned d;
    asm("add.rn.f16x2 %0, %1, %2;" : "=r"(d) : "r"(a), "r"(b));
    return d;
}
// per-half: (z & 0x7FFF) | mask
__device__ __forceinline__ unsigned habsor(unsigned z, unsigned m) {
    unsigned r;
    asm("lop3.b32 %0, %1, 0x7FFF7FFF, %2, 0xEA;" : "=r"(r) : "r"(z), "r"(m));
    return r;
}
// broadcast one f32 into both halves of a half2
__device__ __forceinline__ unsigned bcast_h2(float f) {
    unsigned d;
    asm("cvt.rn.f16x2.f32 %0, %1, %2;" : "=r"(d) : "f"(f), "f"(f));
    return d;
}

// ---------------------------------------------------------------------------
// launch 0: merged setup.
//   block 0:        weight prep (edge fp16 arrays, node arrays, lin, dtype)
//   blocks 1..16:   final-linear vectors (warp per output row)
//   blocks 17+:     zero node accumulators
__global__ void __launch_bounds__(256) k_setup(
    const void* __restrict__ eidx, int n,
    const float* __restrict__ Wl, const float* __restrict__ bl,
    const float* __restrict__ Wr, const float* __restrict__ br,
    const float* __restrict__ We, const float* __restrict__ att,
    const float* __restrict__ bout, const float* __restrict__ Wfc,
    const float* __restrict__ bfc)
{
    const float LOG2E = 1.4426950408889634f;
    const float kap = 0.4f * LOG2E;
    const float lam = 0.6f * LOG2E;
    int bid = blockIdx.x;
    int tid = threadIdx.x;

    if (bid >= 17) {                 // zeroing
        int i = (bid - 17) * 256 + tid;
        if (i < n) {
            g_accum[i] = make_float4(0.f, 0.f, 0.f, 0.f);
            g_degattr[i] = make_float2(0.f, 0.f);
        }
        return;
    }
    if (bid >= 1) {                  // vecA: warp per output row j
        int lane = tid & 31;
        int j = (bid - 1) * 8 + (tid >> 5);
        const float* wrow = Wfc + j * 256;
        float a0 = 0.f, a1 = 0.f, cb = 0.f, d0 = 0.f, d1 = 0.f;
#pragma unroll
        for (int u = 0; u < 8; u++) {
            int idx = u * 32 + lane;
            float w = wrow[idx];
            if (u < 2) {
                a0 += Wl[idx] * w;
                cb += (bl[idx] + bout[idx]) * w;
            } else if (u < 4) {
                a1 += Wl[idx] * w;
                cb += (bl[idx] + bout[idx]) * w;
            } else if (u < 6) {
                int kk = idx - 128;
                cb += (bl[kk] + bout[kk]) * w;
                d0 += Wl[kk] * w;
            } else {
                int kk = idx - 128;
                cb += (bl[kk] + bout[kk]) * w;
                d1 += Wl[kk] * w;
            }
        }
#pragma unroll
        for (int off = 16; off > 0; off >>= 1) {
            a0 += __shfl_xor_sync(0xffffffffu, a0, off);
            a1 += __shfl_xor_sync(0xffffffffu, a1, off);
            cb += __shfl_xor_sync(0xffffffffu, cb, off);
            d0 += __shfl_xor_sync(0xffffffffu, d0, off);
            d1 += __shfl_xor_sync(0xffffffffu, d1, off);
        }
        if (lane == 0) {
            g_A0[j] = a0; g_A1[j] = a1; g_CB[j] = cb + bfc[j];
            g_D0[j] = d0; g_D1[j] = d1;
        }
        return;
    }

    // block 0: weight prep
    if (tid < 64) {
        int c = tid;
        float a0 = att[c], a1 = att[64 + c];
        float k0 = kap * a0, k1 = kap * a1;
        float wl0 = k0 * Wl[c], wl1 = k1 * Wl[64 + c];
        float wr0 = k0 * Wr[c], wr1 = k1 * Wr[64 + c];
        float we0 = k0 * We[c], we1 = k1 * We[64 + c];
        float b0 = k0 * (bl[c] + br[c]), b1 = k1 * (bl[64 + c] + br[64 + c]);

        // fp16 edge weights: half2 {lo=head0, hi=head1}
        __half2 hwl = __floats2half2_rn(wl0, wl1);
        __half2 hwr = __floats2half2_rn(wr0, wr1);
        __half2 hwe = __floats2half2_rn(we0, we1);
        __half2 hb  = __floats2half2_rn(b0,  b1);
        uint4 w;
        w.x = *reinterpret_cast<unsigned*>(&hwl);
        w.y = *reinterpret_cast<unsigned*>(&hwr);
        w.z = *reinterpret_cast<unsigned*>(&hwe);
        w.w = *reinterpret_cast<unsigned*>(&hb);
        g_eW[c] = w;
        unsigned m = (a0 < 0.f ? 0x00008000u : 0u) | (a1 < 0.f ? 0x80000000u : 0u);
        g_eM[c] = m;

        // f32 node weights (self-loop path)
        unsigned m0 = __float_as_uint(a0) & 0x80000000u;
        unsigned m1 = __float_as_uint(a1) & 0x80000000u;
        u64 m2 = ((u64)m1 << 32) | (u64)m0;
        ulonglong2 nA; nA.x = pack2(wl0 + wr0, wl1 + wr1); nA.y = pack2(we0, we1);
        ulonglong2 nB; nB.x = pack2(b0, b1); nB.y = m2;
        g_nA[c] = nA; g_nB[c] = nB;
    }
    if (tid == 0) {
        float Ph[2], Qh[2], Rh[2], Bh[2];
        for (int h = 0; h < 2; h++) {
            float P = 0, Q = 0, R = 0, B = 0;
            for (int c = 0; c < 64; c++) {
                int j = h * 64 + c;
                float aA = att[j];
                P += aA * Wl[j]; Q += aA * Wr[j]; R += aA * We[j];
                B += aA * (bl[j] + br[j]);
            }
            Ph[h] = lam * P; Qh[h] = lam * Q; Rh[h] = lam * R; Bh[h] = lam * B;
        }
        g_linS[0] = Ph[0]; g_linS[1] = Qh[0]; g_linS[2] = Rh[0]; g_linS[3] = Bh[0];
        g_linS[4] = Ph[1]; g_linS[5] = Qh[1]; g_linS[6] = Rh[1]; g_linS[7] = Bh[1];
        g_nlpq = pack2(Ph[0] + Qh[0], Ph[1] + Qh[1]);
        g_nlr  = pack2(Rh[0], Rh[1]);
        g_nlb  = pack2(Bh[0], Bh[1]);
        // edge_index dtype detection (int64 values all < n)
        const u64* p = (const u64*)eidx;
        int is64 = 1;
        for (int k = 0; k < 16; k++)
            if (p[k] >= (u64)n) is64 = 0;
        g_idx64 = is64;
    }
}

// ---------------------------------------------------------------------------
// launch 1: edge pass — fp16 channel loop, heads packed in half2.
// 4 fp16 accumulators per edge (channel strides of 4) bound rounding error.
__global__ void __launch_bounds__(256, 3) k_edges(
    const float* __restrict__ x, const void* __restrict__ eidx,
    const float* __restrict__ eattr, int E)
{
    __shared__ uint4 s_w[64];
    __shared__ unsigned s_m[64];
    int tid = threadIdx.x;
    if (tid < 64) { s_w[tid] = g_eW[tid]; s_m[tid] = g_eM[tid]; }
    __syncthreads();

    int base = (blockIdx.x * blockDim.x + tid) * EPT;
    if (base >= E) return;
    int idx64 = g_idx64;
    const long long* p64 = (const long long*)eidx;
    const int* p32 = (const int*)eidx;

    float sv[EPT], tv[EPT], av[EPT];
    unsigned s2h[EPT], t2h[EPT], a2h[EPT];
    unsigned acc0[EPT], acc1[EPT], acc2[EPT], acc3[EPT];
    int dsti[EPT];

#pragma unroll
    for (int k = 0; k < EPT; k++) {
        int e = base + k; if (e > E - 1) e = E - 1;
        int si, di;
        if (idx64) { si = (int)p64[e]; di = (int)p64[E + e]; }
        else       { si = p32[e];      di = p32[E + e]; }
        dsti[k] = di;
        float aa = eattr[e];
        float s = x[si], t = x[di];
        sv[k] = s; tv[k] = t; av[k] = aa;
        s2h[k] = bcast_h2(s); t2h[k] = bcast_h2(t); a2h[k] = bcast_h2(aa);
        acc0[k] = 0u; acc1[k] = 0u; acc2[k] = 0u; acc3[k] = 0u;
    }

#pragma unroll 2
    for (int c = 0; c < 64; c += 4) {
        uint4 w0 = s_w[c],     w1 = s_w[c + 1];
        uint4 w2 = s_w[c + 2], w3 = s_w[c + 3];
        unsigned m0 = s_m[c],     m1 = s_m[c + 1];
        unsigned m2 = s_m[c + 2], m3 = s_m[c + 3];
#pragma unroll
        for (int k = 0; k < EPT; k++) {
            unsigned z0 = hfma2u(a2h[k], w0.z, w0.w);
            z0 = hfma2u(t2h[k], w0.y, z0);
            z0 = hfma2u(s2h[k], w0.x, z0);
            acc0[k] = hadd2u(acc0[k], habsor(z0, m0));
            unsigned z1 = hfma2u(a2h[k], w1.z, w1.w);
            z1 = hfma2u(t2h[k], w1.y, z1);
            z1 = hfma2u(s2h[k], w1.x, z1);
            acc1[k] = hadd2u(acc1[k], habsor(z1, m1));
            unsigned z2 = hfma2u(a2h[k], w2.z, w2.w);
            z2 = hfma2u(t2h[k], w2.y, z2);
            z2 = hfma2u(s2h[k], w2.x, z2);
            acc2[k] = hadd2u(acc2[k], habsor(z2, m2));
            unsigned z3 = hfma2u(a2h[k], w3.z, w3.w);
            z3 = hfma2u(t2h[k], w3.y, z3);
            z3 = hfma2u(s2h[k], w3.x, z3);
            acc3[k] = hadd2u(acc3[k], habsor(z3, m3));
        }
    }

    // f32 epilogue: linear part, exp2, atomics
    float P0 = g_linS[0], Q0 = g_linS[1], R0 = g_linS[2], B0 = g_linS[3];
    float P1 = g_linS[4], Q1 = g_linS[5], R1 = g_linS[6], B1 = g_linS[7];
#pragma unroll
    for (int k = 0; k < EPT; k++) {
        if (base + k >= E) continue;
        unsigned sum = hadd2u(hadd2u(acc0[k], acc1[k]), hadd2u(acc2[k], acc3[k]));
        __half2 h = *reinterpret_cast<__half2*>(&sum);
        float f0 = __low2float(h), f1 = __high2float(h);
        float s = sv[k], t = tv[k], a = av[k];
        float l0 = f0 + fmaf(s, P0, fmaf(t, Q0, fmaf(a, R0, B0)));
        float l1 = f1 + fmaf(s, P1, fmaf(t, Q1, fmaf(a, R1, B1)));
        float e0 = ex2f(l0), e1 = ex2f(l1);
        atomicAdd(&g_degattr[dsti[k]], make_float2(1.0f, a));
        atomicAdd(&g_accum[dsti[k]], make_float4(e0, e0 * s, e1, e1 * s));
    }
}

// ---------------------------------------------------------------------------
// launch 2: S[target] + folded constant vector Cv (1 block, 128 threads)
__global__ void k_tgt(const float* __restrict__ x, const int* __restrict__ tgtp)
{
    __shared__ float2 sh_S;
    int tid = threadIdx.x;
    int tgt = tgtp[0];   // low 32 bits valid for int32/int64 (LE)
    if (tid < 32) {
        float s = x[tgt];
        float2 da = g_degattr[tgt];
        float am = da.y / fmaxf(da.x, 1.0f);
        u64 s2 = pack2(s, s), a2 = pack2(am, am);
        u64 acc = 0ull;
        for (int c = tid; c < 64; c += 32) {
            ulonglong2 A = g_nA[c], Bv = g_nB[c];
            u64 z = fma2(a2, A.y, Bv.x);
            z = fma2(s2, A.x, z);
            acc = add2(acc, abso2(z, (unsigned)Bv.y, (unsigned)(Bv.y >> 32)));
        }
        float h0, h1; unpack2(acc, h0, h1);
#pragma unroll
        for (int off = 16; off > 0; off >>= 1) {
            h0 += __shfl_xor_sync(0xffffffffu, h0, off);
            h1 += __shfl_xor_sync(0xffffffffu, h1, off);
        }
        u64 f = add2(pack2(h0, h1), fma2(s2, g_nlpq, fma2(a2, g_nlr, g_nlb)));
        float f0, f1; unpack2(f, f0, f1);
        float e0 = ex2f(f0), e1 = ex2f(f1);
        float4 ac = g_accum[tgt];
        if (tid == 0)
            sh_S = make_float2((ac.y + e0 * s) / (ac.x + e0),
                               (ac.w + e1 * s) / (ac.z + e1));
    }
    __syncthreads();
    float2 st = sh_S;
    if (tid < 128)
        g_Cv[tid] = fmaf(st.x, g_D0[tid], fmaf(st.y, g_D1[tid], g_CB[tid]));
}

// ---------------------------------------------------------------------------
// launch 3 (PROFILED): warp-autonomous self-loop/softmax finalize + output.
// Each warp owns 32 nodes; lane j computes S for node base+j in registers,
// then 32 shfl-broadcast iterations write the 512B rows. No block barrier.
__global__ void __launch_bounds__(256) k_nodes_out(
    const float* __restrict__ x, int n, float* __restrict__ out)
{
    __shared__ ulonglong2 s_A[64], s_B[64];
    int tid = threadIdx.x;
    if (tid < 64) { s_A[tid] = g_nA[tid]; s_B[tid] = g_nB[tid]; }
    __syncthreads();   // weight staging only

    int lane = tid & 31;
    int warp = (blockIdx.x * 256 + tid) >> 5;
    int base = warp * 32;
    if (base >= n) return;

    // ---- phase 1: per-lane S for node base+lane ----
    float2 sS;
    {
        int i = base + lane;
        int ii = (i < n) ? i : (n - 1);
        float s = x[ii];
        float2 da = g_degattr[ii];
        float4 ac = g_accum[ii];

        float am = da.y / fmaxf(da.x, 1.0f);
        u64 s2 = pack2(s, s), a2 = pack2(am, am);
        u64 acc0 = 0ull, acc1 = 0ull, acc2 = 0ull, acc3 = 0ull;
#pragma unroll 2
        for (int c = 0; c < 64; c += 4) {
            ulonglong2 A0 = s_A[c],     B0 = s_B[c];
            ulonglong2 A1 = s_A[c + 1], B1 = s_B[c + 1];
            ulonglong2 A2 = s_A[c + 2], B2 = s_B[c + 2];
            ulonglong2 A3 = s_A[c + 3], B3 = s_B[c + 3];
            u64 z0 = fma2(s2, A0.x, fma2(a2, A0.y, B0.x));
            u64 z1 = fma2(s2, A1.x, fma2(a2, A1.y, B1.x));
            u64 z2 = fma2(s2, A2.x, fma2(a2, A2.y, B2.x));
            u64 z3 = fma2(s2, A3.x, fma2(a2, A3.y, B3.x));
            acc0 = add2(acc0, abso2(z0, (unsigned)B0.y, (unsigned)(B0.y >> 32)));
            acc1 = add2(acc1, abso2(z1, (unsigned)B1.y, (unsigned)(B1.y >> 32)));
            acc2 = add2(acc2, abso2(z2, (unsigned)B2.y, (unsigned)(B2.y >> 32)));
            acc3 = add2(acc3, abso2(z3, (unsigned)B3.y, (unsigned)(B3.y >> 32)));
        }
        u64 f = add2(add2(acc0, acc1), add2(acc2, acc3));
        f = add2(f, fma2(s2, g_nlpq, fma2(a2, g_nlr, g_nlb)));
        float f0, f1; unpack2(f, f0, f1);
        float e0 = ex2f(f0), e1 = ex2f(f1);
        sS = make_float2((ac.y + e0 * s) / (ac.x + e0),
                         (ac.w + e1 * s) / (ac.z + e1));
    }

    // ---- phase 2: shfl-broadcast, 512B row per iteration ----
    ulonglong2 A0v = ((const ulonglong2*)g_A0)[lane];
    ulonglong2 A1v = ((const ulonglong2*)g_A1)[lane];
    ulonglong2 Cv  = ((const ulonglong2*)g_Cv)[lane];
    ulonglong2* o2p = (ulonglong2*)out;
    if (base + 32 <= n) {
#pragma unroll 8
        for (int j = 0; j < 32; j++) {
            float sx = __shfl_sync(0xffffffffu, sS.x, j);
            float sy = __shfl_sync(0xffffffffu, sS.y, j);
            u64 sx2 = pack2(sx, sx), sy2 = pack2(sy, sy);
            ulonglong2 o;
            o.x = fma2(sx2, A0v.x, fma2(sy2, A1v.x, Cv.x));
            o.y = fma2(sx2, A0v.y, fma2(sy2, A1v.y, Cv.y));
            o2p[(long long)(base + j) * 32 + lane] = o;
        }
    } else {
        for (int j = 0; j < 32; j++) {
            int node = base + j;
            if (node >= n) break;
            float sx = __shfl_sync(0xffffffffu, sS.x, j);
            float sy = __shfl_sync(0xffffffffu, sS.y, j);
            u64 sx2 = pack2(sx, sx), sy2 = pack2(sy, sy);
            ulonglong2 o;
            o.x = fma2(sx2, A0v.x, fma2(sy2, A1v.x, Cv.x));
            o.y = fma2(sx2, A0v.y, fma2(sy2, A1v.y, Cv.y));
            o2p[(long long)node * 32 + lane] = o;
        }
    }
}

// ---------------------------------------------------------------------------
extern "C" void kernel_launch(void* const* d_in, const int* in_sizes, int n_in,
                              void* d_out, int out_size)
{
    const float* x     = (const float*)d_in[0];
    const void*  eidx  = d_in[1];
    const float* eattr = (const float*)d_in[2];
    const int*   tgtp  = (const int*)d_in[3];
    const float* Wl    = (const float*)d_in[4];
    const float* bl    = (const float*)d_in[5];
    const float* Wr    = (const float*)d_in[6];
    const float* br    = (const float*)d_in[7];
    const float* We    = (const float*)d_in[8];
    const float* att   = (const float*)d_in[9];
    const float* bout  = (const float*)d_in[10];
    const float* Wfc   = (const float*)d_in[11];
    const float* bfc   = (const float*)d_in[12];

    int n = in_sizes[0];   // N nodes (x is [N,1])
    int E = in_sizes[2];   // edges (edge_attr is [E,1])
    float* out = (float*)d_out;

    int nblk = (n + 255) / 256;
    k_setup<<<nblk + 17, 256>>>(eidx, n, Wl, bl, Wr, br, We, att,
                                bout, Wfc, bfc);                 // idx 0
    int ethreads = (E + EPT - 1) / EPT;
    k_edges<<<(ethreads + 255) / 256, 256>>>(x, eidx, eattr, E); // idx 1
    k_tgt<<<1, 128>>>(x, tgtp);                                  // idx 2
    k_nodes_out<<<nblk, 256>>>(x, n, out);                       // idx 3 (profiled)
}

// round 15
// speedup vs baseline: 1.3992x; 1.0691x over previous
#include <cuda_runtime.h>
#include <cuda_fp16.h>

// ---------------------------------------------------------------------------
// GATv2 (H=2, EMB=64) + fused final linear, collapsed to scalar-per-edge form.
// R15: fp16 nodes_out phase-1 (same rt(HFMA2)=2 lever that won R14) with
//      packed uint4 node weights (1 LDS.128/channel), and k_tgt merged into
//      nodes_out (per-warp redundant target-S + register Cv).
//      Edges/setup = R14-exact.
//
// Per-edge:  logit_h = 0.6*L_h + 0.4*sum_c att_hc*|z_hc|   (LeakyReLU split)
//            z_hc = s*Wl + t*Wr + a*We + b,  L_h = s*P_h + t*Q_h + a*R_h + B_h
// Per-node:  S_ih = sum_e alpha_eh * x[src_e]   (softmax without max-shift)
// Output:    out[i,:] = S_i0*A0 + S_i1*A1 + (CB + T0*D0 + T1*D1)
// ---------------------------------------------------------------------------

#define NODE_CAP 131072
#define EPT 4

typedef unsigned long long u64;

__device__ float4 g_accum[NODE_CAP];    // {den0, num0, den1, num1}
__device__ float2 g_degattr[NODE_CAP];  // {deg, attr_sum}

// --- edge weights, fp16 head-packed (lo=head0, hi=head1), natural order
__device__ uint4    g_eW[64];     // {wl_h2, wr_h2, we_h2, b_h2}
__device__ unsigned g_eM[64];     // sign-or mask (bit15 head0, bit31 head1)
__device__ float    g_linS[8];    // P0,Q0,R0,B0, P1,Q1,R1,B1 (f32)

// --- node (self-loop) weights, fp16 head-packed: {wlr_h2, we_h2, b_h2, mask}
__device__ uint4 g_nW[64];
__device__ float g_nlin[6];       // PQ0,R0,B0, PQ1,R1,B1 (f32)

// --- final linear vectors
__device__ __align__(16) float g_A0[128];
__device__ __align__(16) float g_A1[128];
__device__ __align__(16) float g_CB[128];
__device__ __align__(16) float g_D0[128];
__device__ __align__(16) float g_D1[128];
__device__ int g_idx64;

// ---- f32x2 helpers (output path) ----
__device__ __forceinline__ u64 pack2(float lo, float hi) {
    u64 r;
    asm("mov.b64 %0, {%1, %2};" : "=l"(r) : "r"(__float_as_uint(lo)), "r"(__float_as_uint(hi)));
    return r;
}
__device__ __forceinline__ u64 fma2(u64 a, u64 b, u64 c) {
    u64 d;
    asm("fma.rn.f32x2 %0, %1, %2, %3;" : "=l"(d) : "l"(a), "l"(b), "l"(c));
    return d;
}
__device__ __forceinline__ float ex2f(float x) {
    float r;
    asm("ex2.approx.f32 %0, %1;" : "=f"(r) : "f"(x));
    return r;
}

// ---- fp16x2 helpers ----
__device__ __forceinline__ unsigned hfma2u(unsigned a, unsigned b, unsigned c) {
    unsigned d;
    asm("fma.rn.f16x2 %0, %1, %2, %3;" : "=r"(d) : "r"(a), "r"(b), "r"(c));
    return d;
}
__device__ __forceinline__ unsigned hadd2u(unsigned a, unsigned b) {
    unsigned d;
    asm("add.rn.f16x2 %0, %1, %2;" : "=r"(d) : "r"(a), "r"(b));
    return d;
}
// per-half: (z & 0x7FFF) | mask
__device__ __forceinline__ unsigned habsor(unsigned z, unsigned m) {
    unsigned r;
    asm("lop3.b32 %0, %1, 0x7FFF7FFF, %2, 0xEA;" : "=r"(r) : "r"(z), "r"(m));
    return r;
}
// broadcast one f32 into both halves of a half2
__device__ __forceinline__ unsigned bcast_h2(float f) {
    unsigned d;
    asm("cvt.rn.f16x2.f32 %0, %1, %2;" : "=r"(d) : "f"(f), "f"(f));
    return d;
}
__device__ __forceinline__ void h2_to_f32(unsigned h, float& lo, float& hi) {
    __half2 v = *reinterpret_cast<__half2*>(&h);
    lo = __low2float(v); hi = __high2float(v);
}

// ---------------------------------------------------------------------------
// launch 0: merged setup.
//   block 0:        weight prep (edge/node fp16 arrays, lin, dtype detect)
//   blocks 1..16:   final-linear vectors (warp per output row)
//   blocks 17+:     zero node accumulators
__global__ void __launch_bounds__(256) k_setup(
    const void* __restrict__ eidx, int n,
    const float* __restrict__ Wl, const float* __restrict__ bl,
    const float* __restrict__ Wr, const float* __restrict__ br,
    const float* __restrict__ We, const float* __restrict__ att,
    const float* __restrict__ bout, const float* __restrict__ Wfc,
    const float* __restrict__ bfc)
{
    const float LOG2E = 1.4426950408889634f;
    const float kap = 0.4f * LOG2E;
    const float lam = 0.6f * LOG2E;
    int bid = blockIdx.x;
    int tid = threadIdx.x;

    if (bid >= 17) {                 // zeroing
        int i = (bid - 17) * 256 + tid;
        if (i < n) {
            g_accum[i] = make_float4(0.f, 0.f, 0.f, 0.f);
            g_degattr[i] = make_float2(0.f, 0.f);
        }
        return;
    }
    if (bid >= 1) {                  // vecA: warp per output row j
        int lane = tid & 31;
        int j = (bid - 1) * 8 + (tid >> 5);
        const float* wrow = Wfc + j * 256;
        float a0 = 0.f, a1 = 0.f, cb = 0.f, d0 = 0.f, d1 = 0.f;
#pragma unroll
        for (int u = 0; u < 8; u++) {
            int idx = u * 32 + lane;
            float w = wrow[idx];
            if (u < 2) {
                a0 += Wl[idx] * w;
                cb += (bl[idx] + bout[idx]) * w;
            } else if (u < 4) {
                a1 += Wl[idx] * w;
                cb += (bl[idx] + bout[idx]) * w;
            } else if (u < 6) {
                int kk = idx - 128;
                cb += (bl[kk] + bout[kk]) * w;
                d0 += Wl[kk] * w;
            } else {
                int kk = idx - 128;
                cb += (bl[kk] + bout[kk]) * w;
                d1 += Wl[kk] * w;
            }
        }
#pragma unroll
        for (int off = 16; off > 0; off >>= 1) {
            a0 += __shfl_xor_sync(0xffffffffu, a0, off);
            a1 += __shfl_xor_sync(0xffffffffu, a1, off);
            cb += __shfl_xor_sync(0xffffffffu, cb, off);
            d0 += __shfl_xor_sync(0xffffffffu, d0, off);
            d1 += __shfl_xor_sync(0xffffffffu, d1, off);
        }
        if (lane == 0) {
            g_A0[j] = a0; g_A1[j] = a1; g_CB[j] = cb + bfc[j];
            g_D0[j] = d0; g_D1[j] = d1;
        }
        return;
    }

    // block 0: weight prep
    if (tid < 64) {
        int c = tid;
        float a0 = att[c], a1 = att[64 + c];
        float k0 = kap * a0, k1 = kap * a1;
        float wl0 = k0 * Wl[c], wl1 = k1 * Wl[64 + c];
        float wr0 = k0 * Wr[c], wr1 = k1 * Wr[64 + c];
        float we0 = k0 * We[c], we1 = k1 * We[64 + c];
        float b0 = k0 * (bl[c] + br[c]), b1 = k1 * (bl[64 + c] + br[64 + c]);

        unsigned m = (a0 < 0.f ? 0x00008000u : 0u) | (a1 < 0.f ? 0x80000000u : 0u);

        // fp16 edge weights: half2 {lo=head0, hi=head1}
        __half2 hwl = __floats2half2_rn(wl0, wl1);
        __half2 hwr = __floats2half2_rn(wr0, wr1);
        __half2 hwe = __floats2half2_rn(we0, we1);
        __half2 hb  = __floats2half2_rn(b0,  b1);
        uint4 w;
        w.x = *reinterpret_cast<unsigned*>(&hwl);
        w.y = *reinterpret_cast<unsigned*>(&hwr);
        w.z = *reinterpret_cast<unsigned*>(&hwe);
        w.w = *reinterpret_cast<unsigned*>(&hb);
        g_eW[c] = w;
        g_eM[c] = m;

        // fp16 node weights: {wlr_h2, we_h2, b_h2, mask}
        __half2 hwlr = __floats2half2_rn(wl0 + wr0, wl1 + wr1);
        uint4 nw;
        nw.x = *reinterpret_cast<unsigned*>(&hwlr);
        nw.y = w.z;
        nw.z = w.w;
        nw.w = m;
        g_nW[c] = nw;
    }
    if (tid == 0) {
        float Ph[2], Qh[2], Rh[2], Bh[2];
        for (int h = 0; h < 2; h++) {
            float P = 0, Q = 0, R = 0, B = 0;
            for (int c = 0; c < 64; c++) {
                int j = h * 64 + c;
                float aA = att[j];
                P += aA * Wl[j]; Q += aA * Wr[j]; R += aA * We[j];
                B += aA * (bl[j] + br[j]);
            }
            Ph[h] = lam * P; Qh[h] = lam * Q; Rh[h] = lam * R; Bh[h] = lam * B;
        }
        g_linS[0] = Ph[0]; g_linS[1] = Qh[0]; g_linS[2] = Rh[0]; g_linS[3] = Bh[0];
        g_linS[4] = Ph[1]; g_linS[5] = Qh[1]; g_linS[6] = Rh[1]; g_linS[7] = Bh[1];
        g_nlin[0] = Ph[0] + Qh[0]; g_nlin[1] = Rh[0]; g_nlin[2] = Bh[0];
        g_nlin[3] = Ph[1] + Qh[1]; g_nlin[4] = Rh[1]; g_nlin[5] = Bh[1];
        // edge_index dtype detection (int64 values all < n)
        const u64* p = (const u64*)eidx;
        int is64 = 1;
        for (int k = 0; k < 16; k++)
            if (p[k] >= (u64)n) is64 = 0;
        g_idx64 = is64;
    }
}

// ---------------------------------------------------------------------------
// launch 1: edge pass — fp16 channel loop (R14-exact).
__global__ void __launch_bounds__(256, 3) k_edges(
    const float* __restrict__ x, const void* __restrict__ eidx,
    const float* __restrict__ eattr, int E)
{
    __shared__ uint4 s_w[64];
    __shared__ unsigned s_m[64];
    int tid = threadIdx.x;
    if (tid < 64) { s_w[tid] = g_eW[tid]; s_m[tid] = g_eM[tid]; }
    __syncthreads();

    int base = (blockIdx.x * blockDim.x + tid) * EPT;
    if (base >= E) return;
    int idx64 = g_idx64;
    const long long* p64 = (const long long*)eidx;
    const int* p32 = (const int*)eidx;

    float sv[EPT], tv[EPT], av[EPT];
    unsigned s2h[EPT], t2h[EPT], a2h[EPT];
    unsigned acc0[EPT], acc1[EPT], acc2[EPT], acc3[EPT];
    int dsti[EPT];

#pragma unroll
    for (int k = 0; k < EPT; k++) {
        int e = base + k; if (e > E - 1) e = E - 1;
        int si, di;
        if (idx64) { si = (int)p64[e]; di = (int)p64[E + e]; }
        else       { si = p32[e];      di = p32[E + e]; }
        dsti[k] = di;
        float aa = eattr[e];
        float s = x[si], t = x[di];
        sv[k] = s; tv[k] = t; av[k] = aa;
        s2h[k] = bcast_h2(s); t2h[k] = bcast_h2(t); a2h[k] = bcast_h2(aa);
        acc0[k] = 0u; acc1[k] = 0u; acc2[k] = 0u; acc3[k] = 0u;
    }

#pragma unroll 2
    for (int c = 0; c < 64; c += 4) {
        uint4 w0 = s_w[c],     w1 = s_w[c + 1];
        uint4 w2 = s_w[c + 2], w3 = s_w[c + 3];
        unsigned m0 = s_m[c],     m1 = s_m[c + 1];
        unsigned m2 = s_m[c + 2], m3 = s_m[c + 3];
#pragma unroll
        for (int k = 0; k < EPT; k++) {
            unsigned z0 = hfma2u(a2h[k], w0.z, w0.w);
            z0 = hfma2u(t2h[k], w0.y, z0);
            z0 = hfma2u(s2h[k], w0.x, z0);
            acc0[k] = hadd2u(acc0[k], habsor(z0, m0));
            unsigned z1 = hfma2u(a2h[k], w1.z, w1.w);
            z1 = hfma2u(t2h[k], w1.y, z1);
            z1 = hfma2u(s2h[k], w1.x, z1);
            acc1[k] = hadd2u(acc1[k], habsor(z1, m1));
            unsigned z2 = hfma2u(a2h[k], w2.z, w2.w);
            z2 = hfma2u(t2h[k], w2.y, z2);
            z2 = hfma2u(s2h[k], w2.x, z2);
            acc2[k] = hadd2u(acc2[k], habsor(z2, m2));
            unsigned z3 = hfma2u(a2h[k], w3.z, w3.w);
            z3 = hfma2u(t2h[k], w3.y, z3);
            z3 = hfma2u(s2h[k], w3.x, z3);
            acc3[k] = hadd2u(acc3[k], habsor(z3, m3));
        }
    }

    // f32 epilogue: linear part, exp2, atomics
    float P0 = g_linS[0], Q0 = g_linS[1], R0 = g_linS[2], B0 = g_linS[3];
    float P1 = g_linS[4], Q1 = g_linS[5], R1 = g_linS[6], B1 = g_linS[7];
#pragma unroll
    for (int k = 0; k < EPT; k++) {
        if (base + k >= E) continue;
        unsigned sum = hadd2u(hadd2u(acc0[k], acc1[k]), hadd2u(acc2[k], acc3[k]));
        float f0, f1; h2_to_f32(sum, f0, f1);
        float s = sv[k], t = tv[k], a = av[k];
        float l0 = f0 + fmaf(s, P0, fmaf(t, Q0, fmaf(a, R0, B0)));
        float l1 = f1 + fmaf(s, P1, fmaf(t, Q1, fmaf(a, R1, B1)));
        float e0 = ex2f(l0), e1 = ex2f(l1);
        atomicAdd(&g_degattr[dsti[k]], make_float2(1.0f, a));
        atomicAdd(&g_accum[dsti[k]], make_float4(e0, e0 * s, e1, e1 * s));
    }
}

// ---------------------------------------------------------------------------
// launch 2 (PROFILED): warp-autonomous finalize + output, fp16 phase-1, with
// per-warp redundant target-S (k_tgt merged away).
// Each warp owns 32 nodes: compute T=S[tgt] (2 fp16 ch/lane + shfl reduce),
// fold Cv = CB + T0*D0 + T1*D1 into registers, compute per-lane S, then 32
// shfl-broadcast iterations write the 512B rows. No inter-phase block barrier.
__global__ void __launch_bounds__(256) k_nodes_out(
    const float* __restrict__ x, int n, const int* __restrict__ tgtp,
    float* __restrict__ out)
{
    __shared__ uint4 s_w[64];
    int tid = threadIdx.x;
    if (tid < 64) s_w[tid] = g_nW[tid];
    __syncthreads();   // weight staging only

    int lane = tid & 31;
    int warp = (blockIdx.x * 256 + tid) >> 5;
    int base = warp * 32;
    if (base >= n) return;

    float PQ0 = g_nlin[0], R0 = g_nlin[1], B0 = g_nlin[2];
    float PQ1 = g_nlin[3], R1 = g_nlin[4], B1 = g_nlin[5];

    // ---- per-warp target S ----
    float T0, T1;
    {
        int tgt = tgtp[0];   // low 32 bits valid for int32/int64 (LE)
        float s = x[tgt];
        float2 da = g_degattr[tgt];
        float4 ac = g_accum[tgt];
        float am = da.y / fmaxf(da.x, 1.0f);
        unsigned sh = bcast_h2(s), ah = bcast_h2(am);
        uint4 w0 = s_w[lane], w1 = s_w[lane + 32];
        unsigned z0 = hfma2u(sh, w0.x, hfma2u(ah, w0.y, w0.z));
        unsigned z1 = hfma2u(sh, w1.x, hfma2u(ah, w1.y, w1.z));
        unsigned acc = hadd2u(habsor(z0, w0.w), habsor(z1, w1.w));
        float h0, h1; h2_to_f32(acc, h0, h1);
#pragma unroll
        for (int off = 16; off > 0; off >>= 1) {
            h0 += __shfl_xor_sync(0xffffffffu, h0, off);
            h1 += __shfl_xor_sync(0xffffffffu, h1, off);
        }
        float l0 = h0 + fmaf(s, PQ0, fmaf(am, R0, B0));
        float l1 = h1 + fmaf(s, PQ1, fmaf(am, R1, B1));
        float e0 = ex2f(l0), e1 = ex2f(l1);
        T0 = (ac.y + e0 * s) / (ac.x + e0);
        T1 = (ac.w + e1 * s) / (ac.z + e1);
    }

    // ---- phase 1: per-lane S for node base+lane (fp16 channel loop) ----
    float2 sS;
    {
        int i = base + lane;
        int ii = (i < n) ? i : (n - 1);
        float s = x[ii];
        float2 da = g_degattr[ii];
        float4 ac = g_accum[ii];

        float am = da.y / fmaxf(da.x, 1.0f);
        unsigned sh = bcast_h2(s), ah = bcast_h2(am);
        unsigned acc0 = 0u, acc1 = 0u, acc2 = 0u, acc3 = 0u;
#pragma unroll 2
        for (int c = 0; c < 64; c += 4) {
            uint4 w0 = s_w[c],     w1 = s_w[c + 1];
            uint4 w2 = s_w[c + 2], w3 = s_w[c + 3];
            unsigned z0 = hfma2u(sh, w0.x, hfma2u(ah, w0.y, w0.z));
            unsigned z1 = hfma2u(sh, w1.x, hfma2u(ah, w1.y, w1.z));
            unsigned z2 = hfma2u(sh, w2.x, hfma2u(ah, w2.y, w2.z));
            unsigned z3 = hfma2u(sh, w3.x, hfma2u(ah, w3.y, w3.z));
            acc0 = hadd2u(acc0, habsor(z0, w0.w));
            acc1 = hadd2u(acc1, habsor(z1, w1.w));
            acc2 = hadd2u(acc2, habsor(z2, w2.w));
            acc3 = hadd2u(acc3, habsor(z3, w3.w));
        }
        unsigned sum = hadd2u(hadd2u(acc0, acc1), hadd2u(acc2, acc3));
        float f0, f1; h2_to_f32(sum, f0, f1);
        float l0 = f0 + fmaf(s, PQ0, fmaf(am, R0, B0));
        float l1 = f1 + fmaf(s, PQ1, fmaf(am, R1, B1));
        float e0 = ex2f(l0), e1 = ex2f(l1);
        sS = make_float2((ac.y + e0 * s) / (ac.x + e0),
                         (ac.w + e1 * s) / (ac.z + e1));
    }

    // ---- phase 2: shfl-broadcast, 512B row per iteration (f32x2) ----
    ulonglong2 A0v = ((const ulonglong2*)g_A0)[lane];
    ulonglong2 A1v = ((const ulonglong2*)g_A1)[lane];
    ulonglong2 CBv = ((const ulonglong2*)g_CB)[lane];
    ulonglong2 D0v = ((const ulonglong2*)g_D0)[lane];
    ulonglong2 D1v = ((const ulonglong2*)g_D1)[lane];
    u64 T02 = pack2(T0, T0), T12 = pack2(T1, T1);
    ulonglong2 Cv;
    Cv.x = fma2(T02, D0v.x, fma2(T12, D1v.x, CBv.x));
    Cv.y = fma2(T02, D0v.y, fma2(T12, D1v.y, CBv.y));

    ulonglong2* o2p = (ulonglong2*)out;
    if (base + 32 <= n) {
#pragma unroll 8
        for (int j = 0; j < 32; j++) {
            float sx = __shfl_sync(0xffffffffu, sS.x, j);
            float sy = __shfl_sync(0xffffffffu, sS.y, j);
            u64 sx2 = pack2(sx, sx), sy2 = pack2(sy, sy);
            ulonglong2 o;
            o.x = fma2(sx2, A0v.x, fma2(sy2, A1v.x, Cv.x));
            o.y = fma2(sx2, A0v.y, fma2(sy2, A1v.y, Cv.y));
            o2p[(long long)(base + j) * 32 + lane] = o;
        }
    } else {
        for (int j = 0; j < 32; j++) {
            int node = base + j;
            if (node >= n) break;
            float sx = __shfl_sync(0xffffffffu, sS.x, j);
            float sy = __shfl_sync(0xffffffffu, sS.y, j);
            u64 sx2 = pack2(sx, sx), sy2 = pack2(sy, sy);
            ulonglong2 o;
            o.x = fma2(sx2, A0v.x, fma2(sy2, A1v.x, Cv.x));
            o.y = fma2(sx2, A0v.y, fma2(sy2, A1v.y, Cv.y));
            o2p[(long long)node * 32 + lane] = o;
        }
    }
}

// ---------------------------------------------------------------------------
extern "C" void kernel_launch(void* const* d_in, const int* in_sizes, int n_in,
                              void* d_out, int out_size)
{
    const float* x     = (const float*)d_in[0];
    const void*  eidx  = d_in[1];
    const float* eattr = (const float*)d_in[2];
    const int*   tgtp  = (const int*)d_in[3];
    const float* Wl    = (const float*)d_in[4];
    const float* bl    = (const float*)d_in[5];
    const float* Wr    = (const float*)d_in[6];
    const float* br    = (const float*)d_in[7];
    const float* We    = (const float*)d_in[8];
    const float* att   = (const float*)d_in[9];
    const float* bout  = (const float*)d_in[10];
    const float* Wfc   = (const float*)d_in[11];
    const float* bfc   = (const float*)d_in[12];

    int n = in_sizes[0];   // N nodes (x is [N,1])
    int E = in_sizes[2];   // edges (edge_attr is [E,1])
    float* out = (float*)d_out;

    int nblk = (n + 255) / 256;
    k_setup<<<nblk + 17, 256>>>(eidx, n, Wl, bl, Wr, br, We, att,
                                bout, Wfc, bfc);                 // idx 0
    int ethreads = (E + EPT - 1) / EPT;
    k_edges<<<(ethreads + 255) / 256, 256>>>(x, eidx, eattr, E); // idx 1
    k_nodes_out<<<nblk, 256>>>(x, n, tgtp, out);                 // idx 2
}

// round 16
// speedup vs baseline: 1.4514x; 1.0373x over previous
#include <cuda_runtime.h>
#include <cuda_fp16.h>

// ---------------------------------------------------------------------------
// GATv2 (H=2, EMB=64) + fused final linear, collapsed to scalar-per-edge form.
// R16: parallelized linear-part reduction in k_setup (was a tid==0 serial loop
//      with ~512 dependent global loads => 7.7us kernel at issue 6.2%).
//      Edges / nodes_out = R15-exact (both near their HFMA2-pipe floors).
//
// Per-edge:  logit_h = 0.6*L_h + 0.4*sum_c att_hc*|z_hc|   (LeakyReLU split)
//            z_hc = s*Wl + t*Wr + a*We + b,  L_h = s*P_h + t*Q_h + a*R_h + B_h
// Per-node:  S_ih = sum_e alpha_eh * x[src_e]   (softmax without max-shift)
// Output:    out[i,:] = S_i0*A0 + S_i1*A1 + (CB + T0*D0 + T1*D1)
// ---------------------------------------------------------------------------

#define NODE_CAP 131072
#define EPT 4

typedef unsigned long long u64;

__device__ float4 g_accum[NODE_CAP];    // {den0, num0, den1, num1}
__device__ float2 g_degattr[NODE_CAP];  // {deg, attr_sum}

// --- edge weights, fp16 head-packed (lo=head0, hi=head1), natural order
__device__ uint4    g_eW[64];     // {wl_h2, wr_h2, we_h2, b_h2}
__device__ unsigned g_eM[64];     // sign-or mask (bit15 head0, bit31 head1)
__device__ float    g_linS[8];    // P0,Q0,R0,B0, P1,Q1,R1,B1 (f32)

// --- node (self-loop) weights, fp16 head-packed: {wlr_h2, we_h2, b_h2, mask}
__device__ uint4 g_nW[64];
__device__ float g_nlin[6];       // PQ0,R0,B0, PQ1,R1,B1 (f32)

// --- final linear vectors
__device__ __align__(16) float g_A0[128];
__device__ __align__(16) float g_A1[128];
__device__ __align__(16) float g_CB[128];
__device__ __align__(16) float g_D0[128];
__device__ __align__(16) float g_D1[128];
__device__ int g_idx64;

// ---- f32x2 helpers (output path) ----
__device__ __forceinline__ u64 pack2(float lo, float hi) {
    u64 r;
    asm("mov.b64 %0, {%1, %2};" : "=l"(r) : "r"(__float_as_uint(lo)), "r"(__float_as_uint(hi)));
    return r;
}
__device__ __forceinline__ u64 fma2(u64 a, u64 b, u64 c) {
    u64 d;
    asm("fma.rn.f32x2 %0, %1, %2, %3;" : "=l"(d) : "l"(a), "l"(b), "l"(c));
    return d;
}
__device__ __forceinline__ float ex2f(float x) {
    float r;
    asm("ex2.approx.f32 %0, %1;" : "=f"(r) : "f"(x));
    return r;
}

// ---- fp16x2 helpers ----
__device__ __forceinline__ unsigned hfma2u(unsigned a, unsigned b, unsigned c) {
    unsigned d;
    asm("fma.rn.f16x2 %0, %1, %2, %3;" : "=r"(d) : "r"(a), "r"(b), "r"(c));
    return d;
}
__device__ __forceinline__ unsigned hadd2u(unsigned a, unsigned b) {
    unsigned d;
    asm("add.rn.f16x2 %0, %1, %2;" : "=r"(d) : "r"(a), "r"(b));
    return d;
}
// per-half: (z & 0x7FFF) | mask
__device__ __forceinline__ unsigned habsor(unsigned z, unsigned m) {
    unsigned r;
    asm("lop3.b32 %0, %1, 0x7FFF7FFF, %2, 0xEA;" : "=r"(r) : "r"(z), "r"(m));
    return r;
}
// broadcast one f32 into both halves of a half2
__device__ __forceinline__ unsigned bcast_h2(float f) {
    unsigned d;
    asm("cvt.rn.f16x2.f32 %0, %1, %2;" : "=r"(d) : "f"(f), "f"(f));
    return d;
}
__device__ __forceinline__ void h2_to_f32(unsigned h, float& lo, float& hi) {
    __half2 v = *reinterpret_cast<__half2*>(&h);
    lo = __low2float(v); hi = __high2float(v);
}

// ---------------------------------------------------------------------------
// launch 0: merged setup.
//   block 0:        weight prep — per-channel work on tid<64, linear part via
//                   shfl reduction across the two warps (no serial loop)
//   blocks 1..16:   final-linear vectors (warp per output row)
//   blocks 17+:     zero node accumulators
__global__ void __launch_bounds__(256) k_setup(
    const void* __restrict__ eidx, int n,
    const float* __restrict__ Wl, const float* __restrict__ bl,
    const float* __restrict__ Wr, const float* __restrict__ br,
    const float* __restrict__ We, const float* __restrict__ att,
    const float* __restrict__ bout, const float* __restrict__ Wfc,
    const float* __restrict__ bfc)
{
    const float LOG2E = 1.4426950408889634f;
    const float kap = 0.4f * LOG2E;
    const float lam = 0.6f * LOG2E;
    int bid = blockIdx.x;
    int tid = threadIdx.x;

    if (bid >= 17) {                 // zeroing
        int i = (bid - 17) * 256 + tid;
        if (i < n) {
            g_accum[i] = make_float4(0.f, 0.f, 0.f, 0.f);
            g_degattr[i] = make_float2(0.f, 0.f);
        }
        return;
    }
    if (bid >= 1) {                  // vecA: warp per output row j
        int lane = tid & 31;
        int j = (bid - 1) * 8 + (tid >> 5);
        const float* wrow = Wfc + j * 256;
        float a0 = 0.f, a1 = 0.f, cb = 0.f, d0 = 0.f, d1 = 0.f;
#pragma unroll
        for (int u = 0; u < 8; u++) {
            int idx = u * 32 + lane;
            float w = wrow[idx];
            if (u < 2) {
                a0 += Wl[idx] * w;
                cb += (bl[idx] + bout[idx]) * w;
            } else if (u < 4) {
                a1 += Wl[idx] * w;
                cb += (bl[idx] + bout[idx]) * w;
            } else if (u < 6) {
                int kk = idx - 128;
                cb += (bl[kk] + bout[kk]) * w;
                d0 += Wl[kk] * w;
            } else {
                int kk = idx - 128;
                cb += (bl[kk] + bout[kk]) * w;
                d1 += Wl[kk] * w;
            }
        }
#pragma unroll
        for (int off = 16; off > 0; off >>= 1) {
            a0 += __shfl_xor_sync(0xffffffffu, a0, off);
            a1 += __shfl_xor_sync(0xffffffffu, a1, off);
            cb += __shfl_xor_sync(0xffffffffu, cb, off);
            d0 += __shfl_xor_sync(0xffffffffu, d0, off);
            d1 += __shfl_xor_sync(0xffffffffu, d1, off);
        }
        if (lane == 0) {
            g_A0[j] = a0; g_A1[j] = a1; g_CB[j] = cb + bfc[j];
            g_D0[j] = d0; g_D1[j] = d1;
        }
        return;
    }

    // ---- block 0: weight prep, fully parallel ----
    __shared__ float sh_part[2][8];   // per-warp partials: P0,Q0,R0,B0,P1,Q1,R1,B1
    float p0 = 0.f, q0 = 0.f, r0 = 0.f, b0s = 0.f;
    float p1 = 0.f, q1 = 0.f, r1 = 0.f, b1s = 0.f;

    if (tid < 64) {
        int c = tid;
        float a0 = att[c], a1 = att[64 + c];
        float wlA = Wl[c], wlB = Wl[64 + c];
        float wrA = Wr[c], wrB = Wr[64 + c];
        float weA = We[c], weB = We[64 + c];
        float blA = bl[c] + br[c], blB = bl[64 + c] + br[64 + c];

        // linear-part contributions (pre-lam scaling; applied after reduce)
        p0 = a0 * wlA;  q0 = a0 * wrA;  r0 = a0 * weA;  b0s = a0 * blA;
        p1 = a1 * wlB;  q1 = a1 * wrB;  r1 = a1 * weB;  b1s = a1 * blB;

        float k0 = kap * a0, k1 = kap * a1;
        float wl0 = k0 * wlA, wl1 = k1 * wlB;
        float wr0 = k0 * wrA, wr1 = k1 * wrB;
        float we0 = k0 * weA, we1 = k1 * weB;
        float bb0 = k0 * blA, bb1 = k1 * blB;

        unsigned m = (a0 < 0.f ? 0x00008000u : 0u) | (a1 < 0.f ? 0x80000000u : 0u);

        __half2 hwl = __floats2half2_rn(wl0, wl1);
        __half2 hwr = __floats2half2_rn(wr0, wr1);
        __half2 hwe = __floats2half2_rn(we0, we1);
        __half2 hb  = __floats2half2_rn(bb0, bb1);
        uint4 w;
        w.x = *reinterpret_cast<unsigned*>(&hwl);
        w.y = *reinterpret_cast<unsigned*>(&hwr);
        w.z = *reinterpret_cast<unsigned*>(&hwe);
        w.w = *reinterpret_cast<unsigned*>(&hb);
        g_eW[c] = w;
        g_eM[c] = m;

        __half2 hwlr = __floats2half2_rn(wl0 + wr0, wl1 + wr1);
        uint4 nw;
        nw.x = *reinterpret_cast<unsigned*>(&hwlr);
        nw.y = w.z;
        nw.z = w.w;
        nw.w = m;
        g_nW[c] = nw;
    }

    // reduce linear parts across the 64 active threads (2 warps)
    if (tid < 64) {
#pragma unroll
        for (int off = 16; off > 0; off >>= 1) {
            p0 += __shfl_xor_sync(0xffffffffu, p0, off);
            q0 += __shfl_xor_sync(0xffffffffu, q0, off);
            r0 += __shfl_xor_sync(0xffffffffu, r0, off);
            b0s += __shfl_xor_sync(0xffffffffu, b0s, off);
            p1 += __shfl_xor_sync(0xffffffffu, p1, off);
            q1 += __shfl_xor_sync(0xffffffffu, q1, off);
            r1 += __shfl_xor_sync(0xffffffffu, r1, off);
            b1s += __shfl_xor_sync(0xffffffffu, b1s, off);
        }
        if ((tid & 31) == 0) {
            int wrp = tid >> 5;
            sh_part[wrp][0] = p0; sh_part[wrp][1] = q0;
            sh_part[wrp][2] = r0; sh_part[wrp][3] = b0s;
            sh_part[wrp][4] = p1; sh_part[wrp][5] = q1;
            sh_part[wrp][6] = r1; sh_part[wrp][7] = b1s;
        }
    }
    __syncthreads();
    if (tid == 0) {
        float P0 = lam * (sh_part[0][0] + sh_part[1][0]);
        float Q0 = lam * (sh_part[0][1] + sh_part[1][1]);
        float R0 = lam * (sh_part[0][2] + sh_part[1][2]);
        float B0 = lam * (sh_part[0][3] + sh_part[1][3]);
        float P1 = lam * (sh_part[0][4] + sh_part[1][4]);
        float Q1 = lam * (sh_part[0][5] + sh_part[1][5]);
        float R1 = lam * (sh_part[0][6] + sh_part[1][6]);
        float B1 = lam * (sh_part[0][7] + sh_part[1][7]);
        g_linS[0] = P0; g_linS[1] = Q0; g_linS[2] = R0; g_linS[3] = B0;
        g_linS[4] = P1; g_linS[5] = Q1; g_linS[6] = R1; g_linS[7] = B1;
        g_nlin[0] = P0 + Q0; g_nlin[1] = R0; g_nlin[2] = B0;
        g_nlin[3] = P1 + Q1; g_nlin[4] = R1; g_nlin[5] = B1;
        // edge_index dtype detection (int64 values all < n)
        const u64* p = (const u64*)eidx;
        int is64 = 1;
        for (int k = 0; k < 16; k++)
            if (p[k] >= (u64)n) is64 = 0;
        g_idx64 = is64;
    }
}

// ---------------------------------------------------------------------------
// launch 1: edge pass — fp16 channel loop (R14/R15-exact).
__global__ void __launch_bounds__(256, 3) k_edges(
    const float* __restrict__ x, const void* __restrict__ eidx,
    const float* __restrict__ eattr, int E)
{
    __shared__ uint4 s_w[64];
    __shared__ unsigned s_m[64];
    int tid = threadIdx.x;
    if (tid < 64) { s_w[tid] = g_eW[tid]; s_m[tid] = g_eM[tid]; }
    __syncthreads();

    int base = (blockIdx.x * blockDim.x + tid) * EPT;
    if (base >= E) return;
    int idx64 = g_idx64;
    const long long* p64 = (const long long*)eidx;
    const int* p32 = (const int*)eidx;

    float sv[EPT], tv[EPT], av[EPT];
    unsigned s2h[EPT], t2h[EPT], a2h[EPT];
    unsigned acc0[EPT], acc1[EPT], acc2[EPT], acc3[EPT];
    int dsti[EPT];

#pragma unroll
    for (int k = 0; k < EPT; k++) {
        int e = base + k; if (e > E - 1) e = E - 1;
        int si, di;
        if (idx64) { si = (int)p64[e]; di = (int)p64[E + e]; }
        else       { si = p32[e];      di = p32[E + e]; }
        dsti[k] = di;
        float aa = eattr[e];
        float s = x[si], t = x[di];
        sv[k] = s; tv[k] = t; av[k] = aa;
        s2h[k] = bcast_h2(s); t2h[k] = bcast_h2(t); a2h[k] = bcast_h2(aa);
        acc0[k] = 0u; acc1[k] = 0u; acc2[k] = 0u; acc3[k] = 0u;
    }

#pragma unroll 2
    for (int c = 0; c < 64; c += 4) {
        uint4 w0 = s_w[c],     w1 = s_w[c + 1];
        uint4 w2 = s_w[c + 2], w3 = s_w[c + 3];
        unsigned m0 = s_m[c],     m1 = s_m[c + 1];
        unsigned m2 = s_m[c + 2], m3 = s_m[c + 3];
#pragma unroll
        for (int k = 0; k < EPT; k++) {
            unsigned z0 = hfma2u(a2h[k], w0.z, w0.w);
            z0 = hfma2u(t2h[k], w0.y, z0);
            z0 = hfma2u(s2h[k], w0.x, z0);
            acc0[k] = hadd2u(acc0[k], habsor(z0, m0));
            unsigned z1 = hfma2u(a2h[k], w1.z, w1.w);
            z1 = hfma2u(t2h[k], w1.y, z1);
            z1 = hfma2u(s2h[k], w1.x, z1);
            acc1[k] = hadd2u(acc1[k], habsor(z1, m1));
            unsigned z2 = hfma2u(a2h[k], w2.z, w2.w);
            z2 = hfma2u(t2h[k], w2.y, z2);
            z2 = hfma2u(s2h[k], w2.x, z2);
            acc2[k] = hadd2u(acc2[k], habsor(z2, m2));
            unsigned z3 = hfma2u(a2h[k], w3.z, w3.w);
            z3 = hfma2u(t2h[k], w3.y, z3);
            z3 = hfma2u(s2h[k], w3.x, z3);
            acc3[k] = hadd2u(acc3[k], habsor(z3, m3));
        }
    }

    // f32 epilogue: linear part, exp2, atomics
    float P0 = g_linS[0], Q0 = g_linS[1], R0 = g_linS[2], B0 = g_linS[3];
    float P1 = g_linS[4], Q1 = g_linS[5], R1 = g_linS[6], B1 = g_linS[7];
#pragma unroll
    for (int k = 0; k < EPT; k++) {
        if (base + k >= E) continue;
        unsigned sum = hadd2u(hadd2u(acc0[k], acc1[k]), hadd2u(acc2[k], acc3[k]));
        float f0, f1; h2_to_f32(sum, f0, f1);
        float s = sv[k], t = tv[k], a = av[k];
        float l0 = f0 + fmaf(s, P0, fmaf(t, Q0, fmaf(a, R0, B0)));
        float l1 = f1 + fmaf(s, P1, fmaf(t, Q1, fmaf(a, R1, B1)));
        float e0 = ex2f(l0), e1 = ex2f(l1);
        atomicAdd(&g_degattr[dsti[k]], make_float2(1.0f, a));
        atomicAdd(&g_accum[dsti[k]], make_float4(e0, e0 * s, e1, e1 * s));
    }
}

// ---------------------------------------------------------------------------
// launch 2: warp-autonomous finalize + output (R15-exact).
__global__ void __launch_bounds__(256) k_nodes_out(
    const float* __restrict__ x, int n, const int* __restrict__ tgtp,
    float* __restrict__ out)
{
    __shared__ uint4 s_w[64];
    int tid = threadIdx.x;
    if (tid < 64) s_w[tid] = g_nW[tid];
    __syncthreads();   // weight staging only

    int lane = tid & 31;
    int warp = (blockIdx.x * 256 + tid) >> 5;
    int base = warp * 32;
    if (base >= n) return;

    float PQ0 = g_nlin[0], R0 = g_nlin[1], B0 = g_nlin[2];
    float PQ1 = g_nlin[3], R1 = g_nlin[4], B1 = g_nlin[5];

    // ---- per-warp target S ----
    float T0, T1;
    {
        int tgt = tgtp[0];   // low 32 bits valid for int32/int64 (LE)
        float s = x[tgt];
        float2 da = g_degattr[tgt];
        float4 ac = g_accum[tgt];
        float am = da.y / fmaxf(da.x, 1.0f);
        unsigned sh = bcast_h2(s), ah = bcast_h2(am);
        uint4 w0 = s_w[lane], w1 = s_w[lane + 32];
        unsigned z0 = hfma2u(sh, w0.x, hfma2u(ah, w0.y, w0.z));
        unsigned z1 = hfma2u(sh, w1.x, hfma2u(ah, w1.y, w1.z));
        unsigned acc = hadd2u(habsor(z0, w0.w), habsor(z1, w1.w));
        float h0, h1; h2_to_f32(acc, h0, h1);
#pragma unroll
        for (int off = 16; off > 0; off >>= 1) {
            h0 += __shfl_xor_sync(0xffffffffu, h0, off);
            h1 += __shfl_xor_sync(0xffffffffu, h1, off);
        }
        float l0 = h0 + fmaf(s, PQ0, fmaf(am, R0, B0));
        float l1 = h1 + fmaf(s, PQ1, fmaf(am, R1, B1));
        float e0 = ex2f(l0), e1 = ex2f(l1);
        T0 = (ac.y + e0 * s) / (ac.x + e0);
        T1 = (ac.w + e1 * s) / (ac.z + e1);
    }

    // ---- phase 1: per-lane S for node base+lane (fp16 channel loop) ----
    float2 sS;
    {
        int i = base + lane;
        int ii = (i < n) ? i : (n - 1);
        float s = x[ii];
        float2 da = g_degattr[ii];
        float4 ac = g_accum[ii];

        float am = da.y / fmaxf(da.x, 1.0f);
        unsigned sh = bcast_h2(s), ah = bcast_h2(am);
        unsigned acc0 = 0u, acc1 = 0u, acc2 = 0u, acc3 = 0u;
#pragma unroll 2
        for (int c = 0; c < 64; c += 4) {
            uint4 w0 = s_w[c],     w1 = s_w[c + 1];
            uint4 w2 = s_w[c + 2], w3 = s_w[c + 3];
            unsigned z0 = hfma2u(sh, w0.x, hfma2u(ah, w0.y, w0.z));
            unsigned z1 = hfma2u(sh, w1.x, hfma2u(ah, w1.y, w1.z));
            unsigned z2 = hfma2u(sh, w2.x, hfma2u(ah, w2.y, w2.z));
            unsigned z3 = hfma2u(sh, w3.x, hfma2u(ah, w3.y, w3.z));
            acc0 = hadd2u(acc0, habsor(z0, w0.w));
            acc1 = hadd2u(acc1, habsor(z1, w1.w));
            acc2 = hadd2u(acc2, habsor(z2, w2.w));
            acc3 = hadd2u(acc3, habsor(z3, w3.w));
        }
        unsigned sum = hadd2u(hadd2u(acc0, acc1), hadd2u(acc2, acc3));
        float f0, f1; h2_to_f32(sum, f0, f1);
        float l0 = f0 + fmaf(s, PQ0, fmaf(am, R0, B0));
        float l1 = f1 + fmaf(s, PQ1, fmaf(am, R1, B1));
        float e0 = ex2f(l0), e1 = ex2f(l1);
        sS = make_float2((ac.y + e0 * s) / (ac.x + e0),
                         (ac.w + e1 * s) / (ac.z + e1));
    }

    // ---- phase 2: shfl-broadcast, 512B row per iteration (f32x2) ----
    ulonglong2 A0v = ((const ulonglong2*)g_A0)[lane];
    ulonglong2 A1v = ((const ulonglong2*)g_A1)[lane];
    ulonglong2 CBv = ((const ulonglong2*)g_CB)[lane];
    ulonglong2 D0v = ((const ulonglong2*)g_D0)[lane];
    ulonglong2 D1v = ((const ulonglong2*)g_D1)[lane];
    u64 T02 = pack2(T0, T0), T12 = pack2(T1, T1);
    ulonglong2 Cv;
    Cv.x = fma2(T02, D0v.x, fma2(T12, D1v.x, CBv.x));
    Cv.y = fma2(T02, D0v.y, fma2(T12, D1v.y, CBv.y));

    ulonglong2* o2p = (ulonglong2*)out;
    if (base + 32 <= n) {
#pragma unroll 8
        for (int j = 0; j < 32; j++) {
            float sx = __shfl_sync(0xffffffffu, sS.x, j);
            float sy = __shfl_sync(0xffffffffu, sS.y, j);
            u64 sx2 = pack2(sx, sx), sy2 = pack2(sy, sy);
            ulonglong2 o;
            o.x = fma2(sx2, A0v.x, fma2(sy2, A1v.x, Cv.x));
            o.y = fma2(sx2, A0v.y, fma2(sy2, A1v.y, Cv.y));
            o2p[(long long)(base + j) * 32 + lane] = o;
        }
    } else {
        for (int j = 0; j < 32; j++) {
            int node = base + j;
            if (node >= n) break;
            float sx = __shfl_sync(0xffffffffu, sS.x, j);
            float sy = __shfl_sync(0xffffffffu, sS.y, j);
            u64 sx2 = pack2(sx, sx), sy2 = pack2(sy, sy);
            ulonglong2 o;
            o.x = fma2(sx2, A0v.x, fma2(sy2, A1v.x, Cv.x));
            o.y = fma2(sx2, A0v.y, fma2(sy2, A1v.y, Cv.y));
            o2p[(long long)node * 32 + lane] = o;
        }
    }
}

// ---------------------------------------------------------------------------
extern "C" void kernel_launch(void* const* d_in, const int* in_sizes, int n_in,
                              void* d_out, int out_size)
{
    const float* x     = (const float*)d_in[0];
    const void*  eidx  = d_in[1];
    const float* eattr = (const float*)d_in[2];
    const int*   tgtp  = (const int*)d_in[3];
    const float* Wl    = (const float*)d_in[4];
    const float* bl    = (const float*)d_in[5];
    const float* Wr    = (const float*)d_in[6];
    const float* br    = (const float*)d_in[7];
    const float* We    = (const float*)d_in[8];
    const float* att   = (const float*)d_in[9];
    const float* bout  = (const float*)d_in[10];
    const float* Wfc   = (const float*)d_in[11];
    const float* bfc   = (const float*)d_in[12];

    int n = in_sizes[0];   // N nodes (x is [N,1])
    int E = in_sizes[2];   // edges (edge_attr is [E,1])
    float* out = (float*)d_out;

    int nblk = (n + 255) / 256;
    k_setup<<<nblk + 17, 256>>>(eidx, n, Wl, bl, Wr, br, We, att,
                                bout, Wfc, bfc);                 // idx 0
    int ethreads = (E + EPT - 1) / EPT;
    k_edges<<<(ethreads + 255) / 256, 256>>>(x, eidx, eattr, E); // idx 1
    k_nodes_out<<<nblk, 256>>>(x, n, tgtp, out);                 // idx 2
}

// round 17
// speedup vs baseline: 1.4583x; 1.0048x over previous
#include <cuda_runtime.h>
#include <cuda_fp16.h>

// ---------------------------------------------------------------------------
// GATv2 (H=2, EMB=64) + fused final linear, collapsed to scalar-per-edge form.
// R17: edges EPT=6 with 2 fp16 acc chains (LDS amortization 0.625->0.417
//      issues/edge-channel, gather MLP 6, lb(256,3) ~74 regs); epilogue t,a
//      recovered from half2 (error ~5e-6 on logit). nodes_out: constant-vector
//      loads hoisted above phase 1. Setup = R16-exact.
//
// Per-edge:  logit_h = 0.6*L_h + 0.4*sum_c att_hc*|z_hc|   (LeakyReLU split)
//            z_hc = s*Wl + t*Wr + a*We + b,  L_h = s*P_h + t*Q_h + a*R_h + B_h
// Per-node:  S_ih = sum_e alpha_eh * x[src_e]   (softmax without max-shift)
// Output:    out[i,:] = S_i0*A0 + S_i1*A1 + (CB + T0*D0 + T1*D1)
// ---------------------------------------------------------------------------

#define NODE_CAP 131072
#define EPT 6

typedef unsigned long long u64;

__device__ float4 g_accum[NODE_CAP];    // {den0, num0, den1, num1}
__device__ float2 g_degattr[NODE_CAP];  // {deg, attr_sum}

// --- edge weights, fp16 head-packed (lo=head0, hi=head1), natural order
__device__ uint4    g_eW[64];     // {wl_h2, wr_h2, we_h2, b_h2}
__device__ unsigned g_eM[64];     // sign-or mask (bit15 head0, bit31 head1)
__device__ float    g_linS[8];    // P0,Q0,R0,B0, P1,Q1,R1,B1 (f32)

// --- node (self-loop) weights, fp16 head-packed: {wlr_h2, we_h2, b_h2, mask}
__device__ uint4 g_nW[64];
__device__ float g_nlin[6];       // PQ0,R0,B0, PQ1,R1,B1 (f32)

// --- final linear vectors
__device__ __align__(16) float g_A0[128];
__device__ __align__(16) float g_A1[128];
__device__ __align__(16) float g_CB[128];
__device__ __align__(16) float g_D0[128];
__device__ __align__(16) float g_D1[128];
__device__ int g_idx64;

// ---- f32x2 helpers (output path) ----
__device__ __forceinline__ u64 pack2(float lo, float hi) {
    u64 r;
    asm("mov.b64 %0, {%1, %2};" : "=l"(r) : "r"(__float_as_uint(lo)), "r"(__float_as_uint(hi)));
    return r;
}
__device__ __forceinline__ u64 fma2(u64 a, u64 b, u64 c) {
    u64 d;
    asm("fma.rn.f32x2 %0, %1, %2, %3;" : "=l"(d) : "l"(a), "l"(b), "l"(c));
    return d;
}
__device__ __forceinline__ float ex2f(float x) {
    float r;
    asm("ex2.approx.f32 %0, %1;" : "=f"(r) : "f"(x));
    return r;
}

// ---- fp16x2 helpers ----
__device__ __forceinline__ unsigned hfma2u(unsigned a, unsigned b, unsigned c) {
    unsigned d;
    asm("fma.rn.f16x2 %0, %1, %2, %3;" : "=r"(d) : "r"(a), "r"(b), "r"(c));
    return d;
}
__device__ __forceinline__ unsigned hadd2u(unsigned a, unsigned b) {
    unsigned d;
    asm("add.rn.f16x2 %0, %1, %2;" : "=r"(d) : "r"(a), "r"(b));
    return d;
}
// per-half: (z & 0x7FFF) | mask
__device__ __forceinline__ unsigned habsor(unsigned z, unsigned m) {
    unsigned r;
    asm("lop3.b32 %0, %1, 0x7FFF7FFF, %2, 0xEA;" : "=r"(r) : "r"(z), "r"(m));
    return r;
}
// broadcast one f32 into both halves of a half2
__device__ __forceinline__ unsigned bcast_h2(float f) {
    unsigned d;
    asm("cvt.rn.f16x2.f32 %0, %1, %2;" : "=r"(d) : "f"(f), "f"(f));
    return d;
}
__device__ __forceinline__ void h2_to_f32(unsigned h, float& lo, float& hi) {
    __half2 v = *reinterpret_cast<__half2*>(&h);
    lo = __low2float(v); hi = __high2float(v);
}

// ---------------------------------------------------------------------------
// launch 0: merged setup (R16-exact).
__global__ void __launch_bounds__(256) k_setup(
    const void* __restrict__ eidx, int n,
    const float* __restrict__ Wl, const float* __restrict__ bl,
    const float* __restrict__ Wr, const float* __restrict__ br,
    const float* __restrict__ We, const float* __restrict__ att,
    const float* __restrict__ bout, const float* __restrict__ Wfc,
    const float* __restrict__ bfc)
{
    const float LOG2E = 1.4426950408889634f;
    const float kap = 0.4f * LOG2E;
    const float lam = 0.6f * LOG2E;
    int bid = blockIdx.x;
    int tid = threadIdx.x;

    if (bid >= 17) {                 // zeroing
        int i = (bid - 17) * 256 + tid;
        if (i < n) {
            g_accum[i] = make_float4(0.f, 0.f, 0.f, 0.f);
            g_degattr[i] = make_float2(0.f, 0.f);
        }
        return;
    }
    if (bid >= 1) {                  // vecA: warp per output row j
        int lane = tid & 31;
        int j = (bid - 1) * 8 + (tid >> 5);
        const float* wrow = Wfc + j * 256;
        float a0 = 0.f, a1 = 0.f, cb = 0.f, d0 = 0.f, d1 = 0.f;
#pragma unroll
        for (int u = 0; u < 8; u++) {
            int idx = u * 32 + lane;
            float w = wrow[idx];
            if (u < 2) {
                a0 += Wl[idx] * w;
                cb += (bl[idx] + bout[idx]) * w;
            } else if (u < 4) {
                a1 += Wl[idx] * w;
                cb += (bl[idx] + bout[idx]) * w;
            } else if (u < 6) {
                int kk = idx - 128;
                cb += (bl[kk] + bout[kk]) * w;
                d0 += Wl[kk] * w;
            } else {
                int kk = idx - 128;
                cb += (bl[kk] + bout[kk]) * w;
                d1 += Wl[kk] * w;
            }
        }
#pragma unroll
        for (int off = 16; off > 0; off >>= 1) {
            a0 += __shfl_xor_sync(0xffffffffu, a0, off);
            a1 += __shfl_xor_sync(0xffffffffu, a1, off);
            cb += __shfl_xor_sync(0xffffffffu, cb, off);
            d0 += __shfl_xor_sync(0xffffffffu, d0, off);
            d1 += __shfl_xor_sync(0xffffffffu, d1, off);
        }
        if (lane == 0) {
            g_A0[j] = a0; g_A1[j] = a1; g_CB[j] = cb + bfc[j];
            g_D0[j] = d0; g_D1[j] = d1;
        }
        return;
    }

    // ---- block 0: weight prep, fully parallel ----
    __shared__ float sh_part[2][8];
    float p0 = 0.f, q0 = 0.f, r0 = 0.f, b0s = 0.f;
    float p1 = 0.f, q1 = 0.f, r1 = 0.f, b1s = 0.f;

    if (tid < 64) {
        int c = tid;
        float a0 = att[c], a1 = att[64 + c];
        float wlA = Wl[c], wlB = Wl[64 + c];
        float wrA = Wr[c], wrB = Wr[64 + c];
        float weA = We[c], weB = We[64 + c];
        float blA = bl[c] + br[c], blB = bl[64 + c] + br[64 + c];

        p0 = a0 * wlA;  q0 = a0 * wrA;  r0 = a0 * weA;  b0s = a0 * blA;
        p1 = a1 * wlB;  q1 = a1 * wrB;  r1 = a1 * weB;  b1s = a1 * blB;

        float k0 = kap * a0, k1 = kap * a1;
        float wl0 = k0 * wlA, wl1 = k1 * wlB;
        float wr0 = k0 * wrA, wr1 = k1 * wrB;
        float we0 = k0 * weA, we1 = k1 * weB;
        float bb0 = k0 * blA, bb1 = k1 * blB;

        unsigned m = (a0 < 0.f ? 0x00008000u : 0u) | (a1 < 0.f ? 0x80000000u : 0u);

        __half2 hwl = __floats2half2_rn(wl0, wl1);
        __half2 hwr = __floats2half2_rn(wr0, wr1);
        __half2 hwe = __floats2half2_rn(we0, we1);
        __half2 hb  = __floats2half2_rn(bb0, bb1);
        uint4 w;
        w.x = *reinterpret_cast<unsigned*>(&hwl);
        w.y = *reinterpret_cast<unsigned*>(&hwr);
        w.z = *reinterpret_cast<unsigned*>(&hwe);
        w.w = *reinterpret_cast<unsigned*>(&hb);
        g_eW[c] = w;
        g_eM[c] = m;

        __half2 hwlr = __floats2half2_rn(wl0 + wr0, wl1 + wr1);
        uint4 nw;
        nw.x = *reinterpret_cast<unsigned*>(&hwlr);
        nw.y = w.z;
        nw.z = w.w;
        nw.w = m;
        g_nW[c] = nw;
    }

    if (tid < 64) {
#pragma unroll
        for (int off = 16; off > 0; off >>= 1) {
            p0 += __shfl_xor_sync(0xffffffffu, p0, off);
            q0 += __shfl_xor_sync(0xffffffffu, q0, off);
            r0 += __shfl_xor_sync(0xffffffffu, r0, off);
            b0s += __shfl_xor_sync(0xffffffffu, b0s, off);
            p1 += __shfl_xor_sync(0xffffffffu, p1, off);
            q1 += __shfl_xor_sync(0xffffffffu, q1, off);
            r1 += __shfl_xor_sync(0xffffffffu, r1, off);
            b1s += __shfl_xor_sync(0xffffffffu, b1s, off);
        }
        if ((tid & 31) == 0) {
            int wrp = tid >> 5;
            sh_part[wrp][0] = p0; sh_part[wrp][1] = q0;
            sh_part[wrp][2] = r0; sh_part[wrp][3] = b0s;
            sh_part[wrp][4] = p1; sh_part[wrp][5] = q1;
            sh_part[wrp][6] = r1; sh_part[wrp][7] = b1s;
        }
    }
    __syncthreads();
    if (tid == 0) {
        float P0 = lam * (sh_part[0][0] + sh_part[1][0]);
        float Q0 = lam * (sh_part[0][1] + sh_part[1][1]);
        float R0 = lam * (sh_part[0][2] + sh_part[1][2]);
        float B0 = lam * (sh_part[0][3] + sh_part[1][3]);
        float P1 = lam * (sh_part[0][4] + sh_part[1][4]);
        float Q1 = lam * (sh_part[0][5] + sh_part[1][5]);
        float R1 = lam * (sh_part[0][6] + sh_part[1][6]);
        float B1 = lam * (sh_part[0][7] + sh_part[1][7]);
        g_linS[0] = P0; g_linS[1] = Q0; g_linS[2] = R0; g_linS[3] = B0;
        g_linS[4] = P1; g_linS[5] = Q1; g_linS[6] = R1; g_linS[7] = B1;
        g_nlin[0] = P0 + Q0; g_nlin[1] = R0; g_nlin[2] = B0;
        g_nlin[3] = P1 + Q1; g_nlin[4] = R1; g_nlin[5] = B1;
        const u64* p = (const u64*)eidx;
        int is64 = 1;
        for (int k = 0; k < 16; k++)
            if (p[k] >= (u64)n) is64 = 0;
        g_idx64 = is64;
    }
}

// ---------------------------------------------------------------------------
// launch 1: edge pass — fp16, EPT=6, 2 acc chains, 3 CTAs/SM.
// Epilogue recovers t,a from half2 packs (error ~5e-6 on logit); s kept f32.
__global__ void __launch_bounds__(256, 3) k_edges(
    const float* __restrict__ x, const void* __restrict__ eidx,
    const float* __restrict__ eattr, int E)
{
    __shared__ uint4 s_w[64];
    __shared__ unsigned s_m[64];
    int tid = threadIdx.x;
    if (tid < 64) { s_w[tid] = g_eW[tid]; s_m[tid] = g_eM[tid]; }
    __syncthreads();

    long long base = (long long)(blockIdx.x * blockDim.x + tid) * EPT;
    if (base >= E) return;
    int idx64 = g_idx64;
    const long long* p64 = (const long long*)eidx;
    const int* p32 = (const int*)eidx;

    float sv[EPT];
    unsigned s2h[EPT], t2h[EPT], a2h[EPT];
    unsigned accA[EPT], accB[EPT];
    int dsti[EPT];

#pragma unroll
    for (int k = 0; k < EPT; k++) {
        long long e = base + k; if (e > E - 1) e = E - 1;
        int si, di;
        if (idx64) { si = (int)p64[e]; di = (int)p64[E + e]; }
        else       { si = p32[e];      di = p32[E + e]; }
        dsti[k] = di;
        float aa = eattr[e];
        float s = x[si], t = x[di];
        sv[k] = s;
        s2h[k] = bcast_h2(s); t2h[k] = bcast_h2(t); a2h[k] = bcast_h2(aa);
        accA[k] = 0u; accB[k] = 0u;
    }

#pragma unroll 4
    for (int c = 0; c < 64; c += 2) {
        uint4 w0 = s_w[c], w1 = s_w[c + 1];
        unsigned m0 = s_m[c], m1 = s_m[c + 1];
#pragma unroll
        for (int k = 0; k < EPT; k++) {
            unsigned z0 = hfma2u(a2h[k], w0.z, w0.w);
            z0 = hfma2u(t2h[k], w0.y, z0);
            z0 = hfma2u(s2h[k], w0.x, z0);
            accA[k] = hadd2u(accA[k], habsor(z0, m0));
            unsigned z1 = hfma2u(a2h[k], w1.z, w1.w);
            z1 = hfma2u(t2h[k], w1.y, z1);
            z1 = hfma2u(s2h[k], w1.x, z1);
            accB[k] = hadd2u(accB[k], habsor(z1, m1));
        }
    }

    // f32 epilogue: linear part (t,a from half2), exp2, atomics
    float P0 = g_linS[0], Q0 = g_linS[1], R0 = g_linS[2], B0 = g_linS[3];
    float P1 = g_linS[4], Q1 = g_linS[5], R1 = g_linS[6], B1 = g_linS[7];
#pragma unroll
    for (int k = 0; k < EPT; k++) {
        if (base + k >= E) continue;
        unsigned sum = hadd2u(accA[k], accB[k]);
        float f0, f1; h2_to_f32(sum, f0, f1);
        float s = sv[k];
        float t, a, dum;
        h2_to_f32(t2h[k], t, dum);
        h2_to_f32(a2h[k], a, dum);
        float l0 = f0 + fmaf(s, P0, fmaf(t, Q0, fmaf(a, R0, B0)));
        float l1 = f1 + fmaf(s, P1, fmaf(t, Q1, fmaf(a, R1, B1)));
        float e0 = ex2f(l0), e1 = ex2f(l1);
        atomicAdd(&g_degattr[dsti[k]], make_float2(1.0f, a));
        atomicAdd(&g_accum[dsti[k]], make_float4(e0, e0 * s, e1, e1 * s));
    }
}

// ---------------------------------------------------------------------------
// launch 2: warp-autonomous finalize + output (constant vectors hoisted).
__global__ void __launch_bounds__(256) k_nodes_out(
    const float* __restrict__ x, int n, const int* __restrict__ tgtp,
    float* __restrict__ out)
{
    __shared__ uint4 s_w[64];
    int tid = threadIdx.x;
    if (tid < 64) s_w[tid] = g_nW[tid];
    __syncthreads();   // weight staging only

    int lane = tid & 31;
    int warp = (blockIdx.x * 256 + tid) >> 5;
    int base = warp * 32;
    if (base >= n) return;

    // hoisted independent global loads (hide latency under phase 1)
    ulonglong2 A0v = ((const ulonglong2*)g_A0)[lane];
    ulonglong2 A1v = ((const ulonglong2*)g_A1)[lane];
    ulonglong2 CBv = ((const ulonglong2*)g_CB)[lane];
    ulonglong2 D0v = ((const ulonglong2*)g_D0)[lane];
    ulonglong2 D1v = ((const ulonglong2*)g_D1)[lane];

    float PQ0 = g_nlin[0], R0 = g_nlin[1], B0 = g_nlin[2];
    float PQ1 = g_nlin[3], R1 = g_nlin[4], B1 = g_nlin[5];

    // ---- per-warp target S ----
    float T0, T1;
    {
        int tgt = tgtp[0];   // low 32 bits valid for int32/int64 (LE)
        float s = x[tgt];
        float2 da = g_degattr[tgt];
        float4 ac = g_accum[tgt];
        float am = da.y / fmaxf(da.x, 1.0f);
        unsigned sh = bcast_h2(s), ah = bcast_h2(am);
        uint4 w0 = s_w[lane], w1 = s_w[lane + 32];
        unsigned z0 = hfma2u(sh, w0.x, hfma2u(ah, w0.y, w0.z));
        unsigned z1 = hfma2u(sh, w1.x, hfma2u(ah, w1.y, w1.z));
        unsigned acc = hadd2u(habsor(z0, w0.w), habsor(z1, w1.w));
        float h0, h1; h2_to_f32(acc, h0, h1);
#pragma unroll
        for (int off = 16; off > 0; off >>= 1) {
            h0 += __shfl_xor_sync(0xffffffffu, h0, off);
            h1 += __shfl_xor_sync(0xffffffffu, h1, off);
        }
        float l0 = h0 + fmaf(s, PQ0, fmaf(am, R0, B0));
        float l1 = h1 + fmaf(s, PQ1, fmaf(am, R1, B1));
        float e0 = ex2f(l0), e1 = ex2f(l1);
        T0 = (ac.y + e0 * s) / (ac.x + e0);
        T1 = (ac.w + e1 * s) / (ac.z + e1);
    }

    // ---- phase 1: per-lane S for node base+lane (fp16 channel loop) ----
    float2 sS;
    {
        int i = base + lane;
        int ii = (i < n) ? i : (n - 1);
        float s = x[ii];
        float2 da = g_degattr[ii];
        float4 ac = g_accum[ii];

        float am = da.y / fmaxf(da.x, 1.0f);
        unsigned sh = bcast_h2(s), ah = bcast_h2(am);
        unsigned acc0 = 0u, acc1 = 0u, acc2 = 0u, acc3 = 0u;
#pragma unroll 2
        for (int c = 0; c < 64; c += 4) {
            uint4 w0 = s_w[c],     w1 = s_w[c + 1];
            uint4 w2 = s_w[c + 2], w3 = s_w[c + 3];
            unsigned z0 = hfma2u(sh, w0.x, hfma2u(ah, w0.y, w0.z));
            unsigned z1 = hfma2u(sh, w1.x, hfma2u(ah, w1.y, w1.z));
            unsigned z2 = hfma2u(sh, w2.x, hfma2u(ah, w2.y, w2.z));
            unsigned z3 = hfma2u(sh, w3.x, hfma2u(ah, w3.y, w3.z));
            acc0 = hadd2u(acc0, habsor(z0, w0.w));
            acc1 = hadd2u(acc1, habsor(z1, w1.w));
            acc2 = hadd2u(acc2, habsor(z2, w2.w));
            acc3 = hadd2u(acc3, habsor(z3, w3.w));
        }
        unsigned sum = hadd2u(hadd2u(acc0, acc1), hadd2u(acc2, acc3));
        float f0, f1; h2_to_f32(sum, f0, f1);
        float l0 = f0 + fmaf(s, PQ0, fmaf(am, R0, B0));
        float l1 = f1 + fmaf(s, PQ1, fmaf(am, R1, B1));
        float e0 = ex2f(l0), e1 = ex2f(l1);
        sS = make_float2((ac.y + e0 * s) / (ac.x + e0),
                         (ac.w + e1 * s) / (ac.z + e1));
    }

    // ---- phase 2: shfl-broadcast, 512B row per iteration (f32x2) ----
    u64 T02 = pack2(T0, T0), T12 = pack2(T1, T1);
    ulonglong2 Cv;
    Cv.x = fma2(T02, D0v.x, fma2(T12, D1v.x, CBv.x));
    Cv.y = fma2(T02, D0v.y, fma2(T12, D1v.y, CBv.y));

    ulonglong2* o2p = (ulonglong2*)out;
    if (base + 32 <= n) {
#pragma unroll 8
        for (int j = 0; j < 32; j++) {
            float sx = __shfl_sync(0xffffffffu, sS.x, j);
            float sy = __shfl_sync(0xffffffffu, sS.y, j);
            u64 sx2 = pack2(sx, sx), sy2 = pack2(sy, sy);
            ulonglong2 o;
            o.x = fma2(sx2, A0v.x, fma2(sy2, A1v.x, Cv.x));
            o.y = fma2(sx2, A0v.y, fma2(sy2, A1v.y, Cv.y));
            o2p[(long long)(base + j) * 32 + lane] = o;
        }
    } else {
        for (int j = 0; j < 32; j++) {
            int node = base + j;
            if (node >= n) break;
            float sx = __shfl_sync(0xffffffffu, sS.x, j);
            float sy = __shfl_sync(0xffffffffu, sS.y, j);
            u64 sx2 = pack2(sx, sx), sy2 = pack2(sy, sy);
            ulonglong2 o;
            o.x = fma2(sx2, A0v.x, fma2(sy2, A1v.x, Cv.x));
            o.y = fma2(sx2, A0v.y, fma2(sy2, A1v.y, Cv.y));
            o2p[(long long)node * 32 + lane] = o;
        }
    }
}

// ---------------------------------------------------------------------------
extern "C" void kernel_launch(void* const* d_in, const int* in_sizes, int n_in,
                              void* d_out, int out_size)
{
    const float* x     = (const float*)d_in[0];
    const void*  eidx  = d_in[1];
    const float* eattr = (const float*)d_in[2];
    const int*   tgtp  = (const int*)d_in[3];
    const float* Wl    = (const float*)d_in[4];
    const float* bl    = (const float*)d_in[5];
    const float* Wr    = (const float*)d_in[6];
    const float* br    = (const float*)d_in[7];
    const float* We    = (const float*)d_in[8];
    const float* att   = (const float*)d_in[9];
    const float* bout  = (const float*)d_in[10];
    const float* Wfc   = (const float*)d_in[11];
    const float* bfc   = (const float*)d_in[12];

    int n = in_sizes[0];   // N nodes (x is [N,1])
    int E = in_sizes[2];   // edges (edge_attr is [E,1])
    float* out = (float*)d_out;

    int nblk = (n + 255) / 256;
    k_setup<<<nblk + 17, 256>>>(eidx, n, Wl, bl, Wr, br, We, att,
                                bout, Wfc, bfc);                 // idx 0
    long long ethreads = ((long long)E + EPT - 1) / EPT;
    k_edges<<<(int)((ethreads + 255) / 256), 256>>>(x, eidx, eattr, E); // idx 1
    k_nodes_out<<<nblk, 256>>>(x, n, tgtp, out);                 // idx 2
}